// round 6
// baseline (speedup 1.0000x reference)
#include <cuda_runtime.h>
#include <cuda_bf16.h>
#include <math.h>
#include <stdint.h>

// Problem constants
#define N_TOK 2048
#define HDIM  2048
#define IDIM  1408
#define NEXP  64
#define NGRP  8
#define GSZ   8
#define TOPK  8

// GEMM tiling
#define KC      32                 // bf16 K elems per stage
#define ROWB    80                 // smem row stride bytes (64B data + 16B pad)
#define TILE_SZ (128*ROWB)         // 10240 B
#define STAGE_SZ (4*TILE_SZ)       // Ah,Al,Bh,Bl = 40960 B
#define NSTAGE  3
#define SMEM_TOTAL (NSTAGE*STAGE_SZ)  // 122880 B
#define NC1 (HDIM/KC)              // 64
#define KCI (IDIM/KC)              // 44
#define NC2 (NGRP*KCI)             // 352

// ---------------------------------------------------------------------------
// Device global scratch
// ---------------------------------------------------------------------------
__device__ float g_soft[(size_t)N_TOK * NGRP * GSZ];
__device__ float g_scalar[(size_t)N_TOK * NGRP];
__device__ float g_Pg[(size_t)NGRP * IDIM * GSZ];
__device__ float g_Pu[(size_t)NGRP * IDIM * GSZ];

__device__ __nv_bfloat16 g_xh[(size_t)N_TOK * HDIM];
__device__ __nv_bfloat16 g_xl[(size_t)N_TOK * HDIM];
__device__ __nv_bfloat16 g_wgh[(size_t)NGRP * IDIM * HDIM];
__device__ __nv_bfloat16 g_wgl[(size_t)NGRP * IDIM * HDIM];
__device__ __nv_bfloat16 g_wuh[(size_t)NGRP * IDIM * HDIM];
__device__ __nv_bfloat16 g_wul[(size_t)NGRP * IDIM * HDIM];
__device__ __nv_bfloat16 g_wdh[(size_t)NGRP * HDIM * IDIM];
__device__ __nv_bfloat16 g_wdl[(size_t)NGRP * HDIM * IDIM];
__device__ __nv_bfloat16 g_acth[(size_t)NGRP * N_TOK * IDIM];
__device__ __nv_bfloat16 g_actl[(size_t)NGRP * N_TOK * IDIM];

// ---------------------------------------------------------------------------
// PTX helpers (sm_80-portable only)
// ---------------------------------------------------------------------------
__device__ __forceinline__ uint32_t s2u(const void* p) {
    uint32_t a;
    asm("{ .reg .u64 t; cvta.to.shared.u64 t, %1; cvt.u32.u64 %0, t; }"
        : "=r"(a) : "l"(p));
    return a;
}
__device__ __forceinline__ void cpasync16(uint32_t s, const void* g) {
    asm volatile("cp.async.cg.shared.global [%0], [%1], 16;"
                 :: "r"(s), "l"(g) : "memory");
}
#define CP_COMMIT() asm volatile("cp.async.commit_group;" ::: "memory")
#define CP_WAIT(n)  asm volatile("cp.async.wait_group %0;" :: "n"(n) : "memory")

__device__ __forceinline__ void ldsm4(uint32_t* r, uint32_t addr) {
    asm volatile("ldmatrix.sync.aligned.m8n8.x4.shared.b16 {%0,%1,%2,%3}, [%4];"
                 : "=r"(r[0]), "=r"(r[1]), "=r"(r[2]), "=r"(r[3]) : "r"(addr));
}
__device__ __forceinline__ void mma16816(float* d, const uint32_t* a,
                                         uint32_t b0, uint32_t b1) {
    asm volatile(
        "mma.sync.aligned.m16n8k16.row.col.f32.bf16.bf16.f32 "
        "{%0,%1,%2,%3}, {%4,%5,%6,%7}, {%8,%9}, {%0,%1,%2,%3};"
        : "+f"(d[0]), "+f"(d[1]), "+f"(d[2]), "+f"(d[3])
        : "r"(a[0]), "r"(a[1]), "r"(a[2]), "r"(a[3]), "r"(b0), "r"(b1));
}

// ---------------------------------------------------------------------------
// Prep: fp32 -> bf16 hi/lo split
// ---------------------------------------------------------------------------
__global__ __launch_bounds__(256) void split_bf16(
    const float4* __restrict__ src, uint2* __restrict__ hi, uint2* __restrict__ lo,
    int n4)
{
    for (int i = blockIdx.x * 256 + threadIdx.x; i < n4; i += gridDim.x * 256) {
        float4 v = src[i];
        __nv_bfloat16 h0 = __float2bfloat16(v.x), h1 = __float2bfloat16(v.y);
        __nv_bfloat16 h2 = __float2bfloat16(v.z), h3 = __float2bfloat16(v.w);
        __nv_bfloat16 l0 = __float2bfloat16(v.x - __bfloat162float(h0));
        __nv_bfloat16 l1 = __float2bfloat16(v.y - __bfloat162float(h1));
        __nv_bfloat16 l2 = __float2bfloat16(v.z - __bfloat162float(h2));
        __nv_bfloat16 l3 = __float2bfloat16(v.w - __bfloat162float(h3));
        uint2 H, L;
        H.x = ((uint32_t)__bfloat16_as_ushort(h1) << 16) | __bfloat16_as_ushort(h0);
        H.y = ((uint32_t)__bfloat16_as_ushort(h3) << 16) | __bfloat16_as_ushort(h2);
        L.x = ((uint32_t)__bfloat16_as_ushort(l1) << 16) | __bfloat16_as_ushort(l0);
        L.y = ((uint32_t)__bfloat16_as_ushort(l3) << 16) | __bfloat16_as_ushort(l2);
        hi[i] = H; lo[i] = L;
    }
}

// ---------------------------------------------------------------------------
// Routing
// ---------------------------------------------------------------------------
__global__ __launch_bounds__(256) void moe_route(
    const float* __restrict__ x, const float* __restrict__ gate_w,
    const void* __restrict__ inv_map_raw)
{
    __shared__ float xs[HDIM];
    __shared__ float sc[NEXP];
    __shared__ float we[NEXP];

    const int n = blockIdx.x, tid = threadIdx.x;
    const float4* xr4 = (const float4*)(x + (size_t)n * HDIM);
    for (int i = tid; i < HDIM / 4; i += 256) ((float4*)xs)[i] = xr4[i];
    __syncthreads();

    const int warp = tid >> 5, lane = tid & 31;
    float acc[8];
#pragma unroll
    for (int j = 0; j < 8; j++) acc[j] = 0.f;
    const float* gw = gate_w + (size_t)(warp * 8) * HDIM;
    for (int h = lane; h < HDIM; h += 32) {
        float xv = xs[h];
#pragma unroll
        for (int j = 0; j < 8; j++) acc[j] += xv * gw[(size_t)j * HDIM + h];
    }
#pragma unroll
    for (int j = 0; j < 8; j++) {
        float v = acc[j];
#pragma unroll
        for (int o = 16; o > 0; o >>= 1) v += __shfl_down_sync(0xffffffffu, v, o);
        if (lane == 0) sc[warp * 8 + j] = v;
    }
    __syncthreads();

    if (tid == 0) {
        float mx = -1e30f;
        for (int e = 0; e < NEXP; e++) mx = fmaxf(mx, sc[e]);
        float sum = 0.f;
        for (int e = 0; e < NEXP; e++) { float v = expf(sc[e] - mx); sc[e] = v; sum += v; }
        float inv = 1.f / sum;
        for (int e = 0; e < NEXP; e++) { sc[e] *= inv; we[e] = 0.f; }
        for (int k = 0; k < TOPK; k++) {
            int bi = 0; float bv = sc[0];
            for (int e = 1; e < NEXP; e++) if (sc[e] > bv) { bv = sc[e]; bi = e; }
            we[bi] = bv; sc[bi] = -1.f;
        }
    }
    __syncthreads();

    if (tid < NGRP) {
        const int g = tid;
        const int* im32 = (const int*)inv_map_raw;
        const bool is64 = (im32[1] == 0);
        const long long* im64 = (const long long*)inv_map_raw;
        float f[GSZ]; float ss = 0.f;
#pragma unroll
        for (int s = 0; s < GSZ; s++) {
            const int slot = g * GSZ + s;
            const int e = is64 ? (int)im64[slot] : im32[slot];
            f[s] = we[e]; ss += f[s];
        }
        g_scalar[(size_t)n * NGRP + g] = ss;
        float mx = -1e30f;
#pragma unroll
        for (int s = 0; s < GSZ; s++) {
            float v = (f[s] == 0.f) ? -1e9f : f[s];
            f[s] = v; mx = fmaxf(mx, v);
        }
        float es = 0.f;
#pragma unroll
        for (int s = 0; s < GSZ; s++) { float v = expf(f[s] - mx); f[s] = v; es += v; }
        float inv = 1.f / es;
#pragma unroll
        for (int s = 0; s < GSZ; s++)
            g_soft[((size_t)n * NGRP + g) * GSZ + s] = f[s] * inv;
    }
}

// ---------------------------------------------------------------------------
// P projections (fp32 exact)
// ---------------------------------------------------------------------------
__global__ __launch_bounds__(256) void moe_pproj(
    const float* __restrict__ Wg, const float* __restrict__ Wu,
    const float* __restrict__ M)
{
    const int wid = blockIdx.x * 8 + (threadIdx.x >> 5);
    const int lane = threadIdx.x & 31;
    const int g = wid / IDIM, i = wid % IDIM;

    const float* wgr = Wg + ((size_t)g * IDIM + i) * HDIM;
    const float* wur = Wu + ((size_t)g * IDIM + i) * HDIM;
    const float* mg = M + (size_t)g * HDIM * GSZ;

    float ag[8], au[8];
#pragma unroll
    for (int s = 0; s < 8; s++) { ag[s] = 0.f; au[s] = 0.f; }
    for (int h = lane; h < HDIM; h += 32) {
        float wgv = wgr[h], wuv = wur[h];
        const float4* mr = (const float4*)(mg + (size_t)h * GSZ);
        float4 m0 = mr[0], m1 = mr[1];
        ag[0] += wgv * m0.x; ag[1] += wgv * m0.y; ag[2] += wgv * m0.z; ag[3] += wgv * m0.w;
        ag[4] += wgv * m1.x; ag[5] += wgv * m1.y; ag[6] += wgv * m1.z; ag[7] += wgv * m1.w;
        au[0] += wuv * m0.x; au[1] += wuv * m0.y; au[2] += wuv * m0.z; au[3] += wuv * m0.w;
        au[4] += wuv * m1.x; au[5] += wuv * m1.y; au[6] += wuv * m1.z; au[7] += wuv * m1.w;
    }
#pragma unroll
    for (int s = 0; s < 8; s++) {
#pragma unroll
        for (int o = 16; o > 0; o >>= 1) {
            ag[s] += __shfl_down_sync(0xffffffffu, ag[s], o);
            au[s] += __shfl_down_sync(0xffffffffu, au[s], o);
        }
    }
    if (lane == 0) {
        float* pg = &g_Pg[((size_t)g * IDIM + i) * GSZ];
        float* pu = &g_Pu[((size_t)g * IDIM + i) * GSZ];
#pragma unroll
        for (int s = 0; s < 8; s++) { pg[s] = ag[s]; pu[s] = au[s]; }
    }
}

// ---------------------------------------------------------------------------
// Warp-MMA stage: warp tile 64(m) x 32(n), split-bf16 3-pass over KC=32.
//   smem stage: [Ah | Al | Bh | Bl], each 128 rows x 64B (stride 80B).
//   MMA:LDSM = 48:12 per k16 step.
// ---------------------------------------------------------------------------
__device__ __forceinline__ void mma_stage(uint32_t sbuf, int wm, int wn, int lane,
                                          float acc[4][4][4]) {
    const uint32_t lm = (uint32_t)((lane & 15) * ROWB + (lane >> 4) * 16);
#pragma unroll
    for (int s = 0; s < 2; s++) {
        const uint32_t base = sbuf + lm + s * 32;
        uint32_t ah[4][4], al[4][4], bx[2][4];
        // A hi (64 rows)
#pragma unroll
        for (int mt = 0; mt < 4; mt++)
            ldsm4(ah[mt], base + (wm * 64 + mt * 16) * ROWB);
        // B hi (32 C-cols)
#pragma unroll
        for (int bt = 0; bt < 2; bt++)
            ldsm4(bx[bt], base + 2 * TILE_SZ + (wn * 32 + bt * 16) * ROWB);
        // pass 1: Ah x Bh
#pragma unroll
        for (int mt = 0; mt < 4; mt++)
#pragma unroll
            for (int nt = 0; nt < 4; nt++)
                mma16816(acc[mt][nt], ah[mt],
                         bx[nt >> 1][nt & 1], bx[nt >> 1][2 + (nt & 1)]);
        // A lo
#pragma unroll
        for (int mt = 0; mt < 4; mt++)
            ldsm4(al[mt], base + TILE_SZ + (wm * 64 + mt * 16) * ROWB);
        // pass 2: Al x Bh
#pragma unroll
        for (int mt = 0; mt < 4; mt++)
#pragma unroll
            for (int nt = 0; nt < 4; nt++)
                mma16816(acc[mt][nt], al[mt],
                         bx[nt >> 1][nt & 1], bx[nt >> 1][2 + (nt & 1)]);
        // B lo (reuse bx)
#pragma unroll
        for (int bt = 0; bt < 2; bt++)
            ldsm4(bx[bt], base + 3 * TILE_SZ + (wn * 32 + bt * 16) * ROWB);
        // pass 3: Ah x Bl
#pragma unroll
        for (int mt = 0; mt < 4; mt++)
#pragma unroll
            for (int nt = 0; nt < 4; nt++)
                mma16816(acc[mt][nt], ah[mt],
                         bx[nt >> 1][nt & 1], bx[nt >> 1][2 + (nt & 1)]);
    }
}

// ---------------------------------------------------------------------------
// G1: act[g, n0..+128, i0..+64]. C = 128 tok x 128 cols.
//   B rows (= C cols): per 32-block wn: [0..15]=gate(i0+wn*16+..), [16..31]=up.
//   Warps: wm = wid>>2 (2 x 64 rows), wn = wid&3 (4 x 32 cols).
// ---------------------------------------------------------------------------
__global__ __launch_bounds__(256, 1) void moe_g1_mma()
{
    extern __shared__ char smem[];
    const uint32_t sb = s2u(smem);
    const int tid = threadIdx.x, lane = tid & 31;
    const int wn = (tid >> 5) & 3, wm = tid >> 7;
    const int g = blockIdx.z, i0 = blockIdx.y * 64, n0 = blockIdx.x * 128;

    // loader slots: 8 x 16B per thread per stage
    const __nv_bfloat16* srcs[8];
    uint32_t dsts[8];
#pragma unroll
    for (int i = 0; i < 8; i++) {
        const int id = tid + i * 256;
        const int tile = id >> 9, rr = (id >> 2) & 127, cc = id & 3;
        const __nv_bfloat16* p;
        if (tile == 0)      p = g_xh + (size_t)(n0 + rr) * HDIM;
        else if (tile == 1) p = g_xl + (size_t)(n0 + rr) * HDIM;
        else {
            const int wnr = rr >> 5, within = rr & 31;
            const int irow = i0 + wnr * 16 + (within & 15);
            const bool up = within >= 16;
            const __nv_bfloat16* base =
                (tile == 2) ? (up ? g_wuh : g_wgh) : (up ? g_wul : g_wgl);
            p = base + ((size_t)g * IDIM + irow) * HDIM;
        }
        srcs[i] = p + cc * 8;
        dsts[i] = sb + tile * TILE_SZ + rr * ROWB + cc * 16;
    }

    float acc[4][4][4];
#pragma unroll
    for (int mt = 0; mt < 4; mt++)
#pragma unroll
        for (int nt = 0; nt < 4; nt++)
#pragma unroll
            for (int e = 0; e < 4; e++) acc[mt][nt][e] = 0.f;

    // prologue: stages 0,1
#pragma unroll
    for (int i = 0; i < 8; i++) cpasync16(dsts[i], srcs[i]);
    CP_COMMIT();
#pragma unroll
    for (int i = 0; i < 8; i++) cpasync16(dsts[i] + STAGE_SZ, srcs[i] + KC);
    CP_COMMIT();

    int buf = 0;
    for (int c = 0; c < NC1; c++) {
        CP_WAIT(1);
        __syncthreads();
        mma_stage(sb + buf * STAGE_SZ, wm, wn, lane, acc);
        if (c + 2 < NC1) {
            const int k0 = (c + 2) * KC;
            const uint32_t so = (uint32_t)(((c + 2) % NSTAGE) * STAGE_SZ);
#pragma unroll
            for (int i = 0; i < 8; i++) cpasync16(dsts[i] + so, srcs[i] + k0);
        }
        CP_COMMIT();
        buf = (buf + 1) % NSTAGE;
    }

    // ---- epilogue ----
    __syncthreads();
    float* sPg = (float*)smem;       // 64 x 8
    float* sPu = sPg + 512;
    float* sSf = sPu + 512;          // 128 x 8
    float* sSc = sSf + 1024;         // 128
    if (tid < 128) {
        ((float4*)sPg)[tid] = ((const float4*)(g_Pg + ((size_t)g * IDIM + i0) * GSZ))[tid];
        ((float4*)sPu)[tid] = ((const float4*)(g_Pu + ((size_t)g * IDIM + i0) * GSZ))[tid];
    }
    {
        const int t = tid >> 1, hf = tid & 1;
        ((float4*)sSf)[tid] =
            *(const float4*)(g_soft + ((size_t)(n0 + t) * NGRP + g) * GSZ + hf * 4);
    }
    if (tid < 128) sSc[tid] = g_scalar[(size_t)(n0 + tid) * NGRP + g];
    __syncthreads();

    const int r = lane >> 2, cb = (lane & 3) * 2;
#pragma unroll
    for (int mt = 0; mt < 4; mt++) {
#pragma unroll
        for (int e2 = 0; e2 < 2; e2++) {
            const int trow = wm * 64 + mt * 16 + r + e2 * 8;
            const int n = n0 + trow;
            float sf[8];
#pragma unroll
            for (int s = 0; s < 8; s++) sf[s] = sSf[trow * 8 + s];
            const float scl = sSc[trow];
            __nv_bfloat16* ph = g_acth + ((size_t)g * N_TOK + n) * IDIM + i0;
            __nv_bfloat16* pl = g_actl + ((size_t)g * N_TOK + n) * IDIM + i0;
#pragma unroll
            for (int nt = 0; nt < 2; nt++) {   // gate nt, up nt+2, same i
                __nv_bfloat162 vh, vl;
#pragma unroll
                for (int p = 0; p < 2; p++) {
                    const int il = wn * 16 + nt * 8 + cb + p;
                    float gv = acc[mt][nt][e2 * 2 + p];
                    float uv = acc[mt][nt + 2][e2 * 2 + p];
#pragma unroll
                    for (int s = 0; s < 8; s++) {
                        gv += sf[s] * sPg[il * 8 + s];
                        uv += sf[s] * sPu[il * 8 + s];
                    }
                    const float sig = 1.f / (1.f + expf(-gv));
                    const float a = scl * (gv * sig * uv);
                    const __nv_bfloat16 h = __float2bfloat16(a);
                    const __nv_bfloat16 l = __float2bfloat16(a - __bfloat162float(h));
                    if (p == 0) { vh.x = h; vl.x = l; } else { vh.y = h; vl.y = l; }
                }
                const int il0 = wn * 16 + nt * 8 + cb;
                *(__nv_bfloat162*)(ph + il0) = vh;
                *(__nv_bfloat162*)(pl + il0) = vl;
            }
        }
    }
}

// ---------------------------------------------------------------------------
// G2: y[n0..+128, h0..+128] = sum over (g, k-chunks) act @ Wd^T
// ---------------------------------------------------------------------------
__global__ __launch_bounds__(256, 1) void moe_g2_mma(float* __restrict__ y)
{
    extern __shared__ char smem[];
    const uint32_t sb = s2u(smem);
    const int tid = threadIdx.x, lane = tid & 31;
    const int wn = (tid >> 5) & 3, wm = tid >> 7;
    const int n0 = blockIdx.x * 128, h0 = blockIdx.y * 128;

    const __nv_bfloat16* srcs[8];
    uint32_t dsts[8];
    int tiles[8];
#pragma unroll
    for (int i = 0; i < 8; i++) {
        const int id = tid + i * 256;
        const int tile = id >> 9, rr = (id >> 2) & 127, cc = id & 3;
        const __nv_bfloat16* p;
        if (tile == 0)      p = g_acth + (size_t)(n0 + rr) * IDIM;
        else if (tile == 1) p = g_actl + (size_t)(n0 + rr) * IDIM;
        else if (tile == 2) p = g_wdh + (size_t)(h0 + rr) * IDIM;
        else                p = g_wdl + (size_t)(h0 + rr) * IDIM;
        srcs[i] = p + cc * 8;
        dsts[i] = sb + tile * TILE_SZ + rr * ROWB + cc * 16;
        tiles[i] = tile;
    }

    float acc[4][4][4];
#pragma unroll
    for (int mt = 0; mt < 4; mt++)
#pragma unroll
        for (int nt = 0; nt < 4; nt++)
#pragma unroll
            for (int e = 0; e < 4; e++) acc[mt][nt][e] = 0.f;

    // chunk c -> (g, k): g = c / KCI, k = (c % KCI) * KC
    // prologue: chunks 0,1
#pragma unroll
    for (int i = 0; i < 8; i++) cpasync16(dsts[i], srcs[i]);
    CP_COMMIT();
#pragma unroll
    for (int i = 0; i < 8; i++) cpasync16(dsts[i] + STAGE_SZ, srcs[i] + KC);
    CP_COMMIT();

    int buf = 0;
    for (int c = 0; c < NC2; c++) {
        CP_WAIT(1);
        __syncthreads();
        mma_stage(sb + buf * STAGE_SZ, wm, wn, lane, acc);
        if (c + 2 < NC2) {
            const int cn = c + 2;
            const int gg = cn / KCI, kk = cn - gg * KCI;
            const size_t offA = ((size_t)gg * N_TOK) * IDIM + (size_t)kk * KC;
            const size_t offB = ((size_t)gg * HDIM) * IDIM + (size_t)kk * KC;
            const uint32_t so = (uint32_t)((cn % NSTAGE) * STAGE_SZ);
#pragma unroll
            for (int i = 0; i < 8; i++)
                cpasync16(dsts[i] + so, srcs[i] + (tiles[i] < 2 ? offA : offB));
        }
        CP_COMMIT();
        buf = (buf + 1) % NSTAGE;
    }

    // epilogue: fp32 y
    const int r = lane >> 2, cb = (lane & 3) * 2;
#pragma unroll
    for (int mt = 0; mt < 4; mt++) {
#pragma unroll
        for (int e2 = 0; e2 < 2; e2++) {
            const int n = n0 + wm * 64 + mt * 16 + r + e2 * 8;
            float* row = y + (size_t)n * HDIM + h0 + wn * 32;
#pragma unroll
            for (int nt = 0; nt < 4; nt++) {
                float2 v;
                v.x = acc[mt][nt][e2 * 2];
                v.y = acc[mt][nt][e2 * 2 + 1];
                *(float2*)(row + nt * 8 + cb) = v;
            }
        }
    }
}

// ---------------------------------------------------------------------------
// Launch
// ---------------------------------------------------------------------------
extern "C" void kernel_launch(void* const* d_in, const int* in_sizes, int n_in,
                              void* d_out, int out_size)
{
    const float* x      = (const float*)d_in[0];
    const float* gate_w = (const float*)d_in[1];
    const float* mask_w = (const float*)d_in[2];
    const float* Wg     = (const float*)d_in[3];
    const float* Wu     = (const float*)d_in[4];
    const float* Wd     = (const float*)d_in[5];
    const void*  invmap = (const void*)d_in[6];
    float* y = (float*)d_out;
    (void)in_sizes; (void)n_in; (void)out_size;

    cudaFuncSetAttribute(moe_g1_mma, cudaFuncAttributeMaxDynamicSharedMemorySize, SMEM_TOTAL);
    cudaFuncSetAttribute(moe_g2_mma, cudaFuncAttributeMaxDynamicSharedMemorySize, SMEM_TOTAL);

    __nv_bfloat16 *xh, *xl, *wgh, *wgl, *wuh, *wul, *wdh, *wdl;
    cudaGetSymbolAddress((void**)&xh,  g_xh);
    cudaGetSymbolAddress((void**)&xl,  g_xl);
    cudaGetSymbolAddress((void**)&wgh, g_wgh);
    cudaGetSymbolAddress((void**)&wgl, g_wgl);
    cudaGetSymbolAddress((void**)&wuh, g_wuh);
    cudaGetSymbolAddress((void**)&wul, g_wul);
    cudaGetSymbolAddress((void**)&wdh, g_wdh);
    cudaGetSymbolAddress((void**)&wdl, g_wdl);

    // prep splits
    split_bf16<<<2048, 256>>>((const float4*)x, (uint2*)xh, (uint2*)xl,
                              (int)((size_t)N_TOK * HDIM / 4));
    split_bf16<<<2048, 256>>>((const float4*)Wg, (uint2*)wgh, (uint2*)wgl,
                              (int)((size_t)NGRP * IDIM * HDIM / 4));
    split_bf16<<<2048, 256>>>((const float4*)Wu, (uint2*)wuh, (uint2*)wul,
                              (int)((size_t)NGRP * IDIM * HDIM / 4));
    split_bf16<<<2048, 256>>>((const float4*)Wd, (uint2*)wdh, (uint2*)wdl,
                              (int)((size_t)NGRP * HDIM * IDIM / 4));

    // routing + rank-8 projections
    moe_route<<<N_TOK, 256>>>(x, gate_w, invmap);
    moe_pproj<<<(NGRP * IDIM) / 8, 256>>>(Wg, Wu, mask_w);

    // G1: gate/up warp-MMA GEMM + fused epilogue
    dim3 g1grid(N_TOK / 128, IDIM / 64, NGRP);
    moe_g1_mma<<<g1grid, 256, SMEM_TOTAL>>>();

    // G2: down-proj accumulated over groups
    dim3 g2grid(N_TOK / 128, HDIM / 128);
    moe_g2_mma<<<g2grid, 256, SMEM_TOTAL>>>(y);
}

// round 7
// speedup vs baseline: 1.4126x; 1.4126x over previous
#include <cuda_runtime.h>
#include <cuda_bf16.h>
#include <math.h>
#include <stdint.h>

// Problem constants
#define N_TOK 2048
#define HDIM  2048
#define IDIM  1408
#define NEXP  64
#define NGRP  8
#define GSZ   8
#define TOPK  8

// GEMM tiling (tf32, fp32-in-smem)
#define KC      32                 // fp32 K elems per chunk (128B rows)
#define ROWB    144                // smem row stride bytes (128 data + 16 pad)
#define TILE_SZ (128*ROWB)         // 18432 B
#define STAGE_SZ (2*TILE_SZ)       // A,B = 36864 B
#define SMEM_TOTAL (2*STAGE_SZ)    // 73728 B
#define NC1 (HDIM/KC)              // 64
#define KCI (IDIM/KC)              // 44
#define NC2 (NGRP*KCI)             // 352

// ---------------------------------------------------------------------------
// Device global scratch
// ---------------------------------------------------------------------------
__device__ float g_soft[(size_t)N_TOK * NGRP * GSZ];
__device__ float g_scalar[(size_t)N_TOK * NGRP];
__device__ float g_Pg[(size_t)NGRP * IDIM * GSZ];
__device__ float g_Pu[(size_t)NGRP * IDIM * GSZ];

__device__ float g_xr[(size_t)N_TOK * HDIM];          // tf32-rounded x
__device__ float g_wgr[(size_t)NGRP * IDIM * HDIM];   // tf32-rounded Wg
__device__ float g_wur[(size_t)NGRP * IDIM * HDIM];   // tf32-rounded Wu
__device__ float g_wdr[(size_t)NGRP * HDIM * IDIM];   // tf32-rounded Wd
__device__ float g_act[(size_t)NGRP * N_TOK * IDIM];  // tf32-rounded activations

// ---------------------------------------------------------------------------
// PTX helpers (sm_80-portable only)
// ---------------------------------------------------------------------------
__device__ __forceinline__ uint32_t s2u(const void* p) {
    uint32_t a;
    asm("{ .reg .u64 t; cvta.to.shared.u64 t, %1; cvt.u32.u64 %0, t; }"
        : "=r"(a) : "l"(p));
    return a;
}
__device__ __forceinline__ void cpasync16(uint32_t s, const void* g) {
    asm volatile("cp.async.cg.shared.global [%0], [%1], 16;"
                 :: "r"(s), "l"(g) : "memory");
}
#define CP_COMMIT() asm volatile("cp.async.commit_group;" ::: "memory")
#define CP_WAIT(n)  asm volatile("cp.async.wait_group %0;" :: "n"(n) : "memory")

__device__ __forceinline__ void ldsm4(uint32_t* r, uint32_t addr) {
    asm volatile("ldmatrix.sync.aligned.m8n8.x4.shared.b16 {%0,%1,%2,%3}, [%4];"
                 : "=r"(r[0]), "=r"(r[1]), "=r"(r[2]), "=r"(r[3]) : "r"(addr));
}
// tf32 MMA: D(16x8) += A(16x8) * B(8x8), operands are tf32 bit-patterns in b32
__device__ __forceinline__ void mma1688(float* d, const uint32_t* a,
                                        uint32_t b0, uint32_t b1) {
    asm volatile(
        "mma.sync.aligned.m16n8k8.row.col.f32.tf32.tf32.f32 "
        "{%0,%1,%2,%3}, {%4,%5,%6,%7}, {%8,%9}, {%0,%1,%2,%3};"
        : "+f"(d[0]), "+f"(d[1]), "+f"(d[2]), "+f"(d[3])
        : "r"(a[0]), "r"(a[1]), "r"(a[2]), "r"(a[3]), "r"(b0), "r"(b1));
}
__device__ __forceinline__ uint32_t f2tf(float f) {
    uint32_t r;
    asm("cvt.rna.tf32.f32 %0, %1;" : "=r"(r) : "f"(f));
    return r;
}

// ---------------------------------------------------------------------------
// Prep: round fp32 -> tf32 (stored as fp32 with low mantissa zeroed)
// ---------------------------------------------------------------------------
__global__ __launch_bounds__(256) void tf32_round(
    const float4* __restrict__ src, float4* __restrict__ dst, int n4)
{
    for (int i = blockIdx.x * 256 + threadIdx.x; i < n4; i += gridDim.x * 256) {
        float4 v = src[i];
        float4 o;
        o.x = __uint_as_float(f2tf(v.x));
        o.y = __uint_as_float(f2tf(v.y));
        o.z = __uint_as_float(f2tf(v.z));
        o.w = __uint_as_float(f2tf(v.w));
        dst[i] = o;
    }
}

// ---------------------------------------------------------------------------
// Routing (uses raw fp32 inputs; exact)
// ---------------------------------------------------------------------------
__global__ __launch_bounds__(256) void moe_route(
    const float* __restrict__ x, const float* __restrict__ gate_w,
    const void* __restrict__ inv_map_raw)
{
    __shared__ float xs[HDIM];
    __shared__ float sc[NEXP];
    __shared__ float we[NEXP];

    const int n = blockIdx.x, tid = threadIdx.x;
    const float4* xr4 = (const float4*)(x + (size_t)n * HDIM);
    for (int i = tid; i < HDIM / 4; i += 256) ((float4*)xs)[i] = xr4[i];
    __syncthreads();

    const int warp = tid >> 5, lane = tid & 31;
    float acc[8];
#pragma unroll
    for (int j = 0; j < 8; j++) acc[j] = 0.f;
    const float* gw = gate_w + (size_t)(warp * 8) * HDIM;
    for (int h = lane; h < HDIM; h += 32) {
        float xv = xs[h];
#pragma unroll
        for (int j = 0; j < 8; j++) acc[j] += xv * gw[(size_t)j * HDIM + h];
    }
#pragma unroll
    for (int j = 0; j < 8; j++) {
        float v = acc[j];
#pragma unroll
        for (int o = 16; o > 0; o >>= 1) v += __shfl_down_sync(0xffffffffu, v, o);
        if (lane == 0) sc[warp * 8 + j] = v;
    }
    __syncthreads();

    if (tid == 0) {
        float mx = -1e30f;
        for (int e = 0; e < NEXP; e++) mx = fmaxf(mx, sc[e]);
        float sum = 0.f;
        for (int e = 0; e < NEXP; e++) { float v = expf(sc[e] - mx); sc[e] = v; sum += v; }
        float inv = 1.f / sum;
        for (int e = 0; e < NEXP; e++) { sc[e] *= inv; we[e] = 0.f; }
        for (int k = 0; k < TOPK; k++) {
            int bi = 0; float bv = sc[0];
            for (int e = 1; e < NEXP; e++) if (sc[e] > bv) { bv = sc[e]; bi = e; }
            we[bi] = bv; sc[bi] = -1.f;
        }
    }
    __syncthreads();

    if (tid < NGRP) {
        const int g = tid;
        const int* im32 = (const int*)inv_map_raw;
        const bool is64 = (im32[1] == 0);
        const long long* im64 = (const long long*)inv_map_raw;
        float f[GSZ]; float ss = 0.f;
#pragma unroll
        for (int s = 0; s < GSZ; s++) {
            const int slot = g * GSZ + s;
            const int e = is64 ? (int)im64[slot] : im32[slot];
            f[s] = we[e]; ss += f[s];
        }
        g_scalar[(size_t)n * NGRP + g] = ss;
        float mx = -1e30f;
#pragma unroll
        for (int s = 0; s < GSZ; s++) {
            float v = (f[s] == 0.f) ? -1e9f : f[s];
            f[s] = v; mx = fmaxf(mx, v);
        }
        float es = 0.f;
#pragma unroll
        for (int s = 0; s < GSZ; s++) { float v = expf(f[s] - mx); f[s] = v; es += v; }
        float inv = 1.f / es;
#pragma unroll
        for (int s = 0; s < GSZ; s++)
            g_soft[((size_t)n * NGRP + g) * GSZ + s] = f[s] * inv;
    }
}

// ---------------------------------------------------------------------------
// P projections (fp32 exact)
// ---------------------------------------------------------------------------
__global__ __launch_bounds__(256) void moe_pproj(
    const float* __restrict__ Wg, const float* __restrict__ Wu,
    const float* __restrict__ M)
{
    const int wid = blockIdx.x * 8 + (threadIdx.x >> 5);
    const int lane = threadIdx.x & 31;
    const int g = wid / IDIM, i = wid % IDIM;

    const float* wgr = Wg + ((size_t)g * IDIM + i) * HDIM;
    const float* wur = Wu + ((size_t)g * IDIM + i) * HDIM;
    const float* mg = M + (size_t)g * HDIM * GSZ;

    float ag[8], au[8];
#pragma unroll
    for (int s = 0; s < 8; s++) { ag[s] = 0.f; au[s] = 0.f; }
    for (int h = lane; h < HDIM; h += 32) {
        float wgv = wgr[h], wuv = wur[h];
        const float4* mr = (const float4*)(mg + (size_t)h * GSZ);
        float4 m0 = mr[0], m1 = mr[1];
        ag[0] += wgv * m0.x; ag[1] += wgv * m0.y; ag[2] += wgv * m0.z; ag[3] += wgv * m0.w;
        ag[4] += wgv * m1.x; ag[5] += wgv * m1.y; ag[6] += wgv * m1.z; ag[7] += wgv * m1.w;
        au[0] += wuv * m0.x; au[1] += wuv * m0.y; au[2] += wuv * m0.z; au[3] += wuv * m0.w;
        au[4] += wuv * m1.x; au[5] += wuv * m1.y; au[6] += wuv * m1.z; au[7] += wuv * m1.w;
    }
#pragma unroll
    for (int s = 0; s < 8; s++) {
#pragma unroll
        for (int o = 16; o > 0; o >>= 1) {
            ag[s] += __shfl_down_sync(0xffffffffu, ag[s], o);
            au[s] += __shfl_down_sync(0xffffffffu, au[s], o);
        }
    }
    if (lane == 0) {
        float* pg = &g_Pg[((size_t)g * IDIM + i) * GSZ];
        float* pu = &g_Pu[((size_t)g * IDIM + i) * GSZ];
#pragma unroll
        for (int s = 0; s < 8; s++) { pg[s] = ag[s]; pu[s] = au[s]; }
    }
}

// ---------------------------------------------------------------------------
// tf32 warp-MMA stage: warp tile 64(m) x 32(n), one pass over KC=32.
//   smem stage: [A | B], each 128 rows x 128B fp32 (stride 144B).
//   Fragments via ldmatrix b16-pair trick (each b32 reg = one fp32 value).
// ---------------------------------------------------------------------------
__device__ __forceinline__ void mma_stage(uint32_t sbuf, int wm, int wn, int lane,
                                          float acc[4][4][4]) {
    const uint32_t lm = (uint32_t)((lane & 15) * ROWB + (lane >> 4) * 16);
#pragma unroll
    for (int s = 0; s < 4; s++) {                    // k8 steps
        const uint32_t base = sbuf + lm + s * 32;    // 8 floats per step
        uint32_t a[4][4], bx[2][4];
#pragma unroll
        for (int mt = 0; mt < 4; mt++)
            ldsm4(a[mt], base + (wm * 64 + mt * 16) * ROWB);
#pragma unroll
        for (int bt = 0; bt < 2; bt++)
            ldsm4(bx[bt], base + TILE_SZ + (wn * 32 + bt * 16) * ROWB);
        // bx[bt] = {b0(rows+0..7), b0(rows+8..15), b1(rows+0..7), b1(rows+8..15)}
#pragma unroll
        for (int mt = 0; mt < 4; mt++)
#pragma unroll
            for (int j = 0; j < 4; j++)
                mma1688(acc[mt][j], a[mt], bx[j >> 1][j & 1], bx[j >> 1][2 + (j & 1)]);
    }
}

// ---------------------------------------------------------------------------
// G1: act[g, n0..+128, i0..+64]. C = 128 tok x 128 cols (gate|up per 16).
//   Warps: wn = wid&3 (4 x 32 cols), wm = wid>>2 (2 x 64 rows).
// ---------------------------------------------------------------------------
__global__ __launch_bounds__(256, 1) void moe_g1_mma()
{
    extern __shared__ char smem[];
    const uint32_t sb = s2u(smem);
    const int tid = threadIdx.x, lane = tid & 31;
    const int wn = (tid >> 5) & 3, wm = tid >> 7;
    const int g = blockIdx.z, i0 = blockIdx.y * 64, n0 = blockIdx.x * 128;

    // loader slots: 8 x 16B (4 floats) per thread per stage
    const float* srcs[8];
    uint32_t dsts[8];
#pragma unroll
    for (int i = 0; i < 8; i++) {
        const int id = tid + i * 256;
        const int tile = id >> 10, rr = (id >> 3) & 127, cc = id & 7;
        const float* p;
        if (tile == 0) {
            p = g_xr + (size_t)(n0 + rr) * HDIM;
        } else {
            const int wnr = rr >> 5, within = rr & 31;
            const int irow = i0 + wnr * 16 + (within & 15);
            const float* base = (within < 16) ? g_wgr : g_wur;
            p = base + ((size_t)g * IDIM + irow) * HDIM;
        }
        srcs[i] = p + cc * 4;
        dsts[i] = sb + tile * TILE_SZ + rr * ROWB + cc * 16;
    }

    float acc[4][4][4];
#pragma unroll
    for (int mt = 0; mt < 4; mt++)
#pragma unroll
        for (int j = 0; j < 4; j++)
#pragma unroll
            for (int e = 0; e < 4; e++) acc[mt][j][e] = 0.f;

    // prologue: stage 0
#pragma unroll
    for (int i = 0; i < 8; i++) cpasync16(dsts[i], srcs[i]);
    CP_COMMIT();

    for (int c = 0; c < NC1; c++) {
        const int s = c & 1;
        if (c + 1 < NC1) {
            const int k0 = (c + 1) * KC;
            const uint32_t so = (uint32_t)((1 - s) * STAGE_SZ);
#pragma unroll
            for (int i = 0; i < 8; i++) cpasync16(dsts[i] + so, srcs[i] + k0);
            CP_COMMIT();
            CP_WAIT(1);
        } else {
            CP_WAIT(0);
        }
        __syncthreads();
        mma_stage(sb + s * STAGE_SZ, wm, wn, lane, acc);
        __syncthreads();
    }

    // ---- epilogue: rank-8 correction + silu*up*scalar -> act (tf32-rounded) ----
    float* sPg = (float*)smem;       // 64 x 8
    float* sPu = sPg + 512;
    float* sSf = sPu + 512;          // 128 x 8
    float* sSc = sSf + 1024;         // 128
    if (tid < 128) {
        ((float4*)sPg)[tid] = ((const float4*)(g_Pg + ((size_t)g * IDIM + i0) * GSZ))[tid];
        ((float4*)sPu)[tid] = ((const float4*)(g_Pu + ((size_t)g * IDIM + i0) * GSZ))[tid];
    }
    {
        const int t = tid >> 1, hf = tid & 1;
        ((float4*)sSf)[tid] =
            *(const float4*)(g_soft + ((size_t)(n0 + t) * NGRP + g) * GSZ + hf * 4);
    }
    if (tid < 128) sSc[tid] = g_scalar[(size_t)(n0 + tid) * NGRP + g];
    __syncthreads();

    const int r = lane >> 2, cb = (lane & 3) * 2;
#pragma unroll
    for (int mt = 0; mt < 4; mt++) {
#pragma unroll
        for (int e2 = 0; e2 < 2; e2++) {
            const int trow = wm * 64 + mt * 16 + r + e2 * 8;
            const int n = n0 + trow;
            float sf[8];
#pragma unroll
            for (int s = 0; s < 8; s++) sf[s] = sSf[trow * 8 + s];
            const float scl = sSc[trow];
            float* pa = g_act + ((size_t)g * N_TOK + n) * IDIM + i0;
#pragma unroll
            for (int nt = 0; nt < 2; nt++) {   // gate block nt, up block nt+2
                float2 v;
#pragma unroll
                for (int p = 0; p < 2; p++) {
                    const int il = wn * 16 + nt * 8 + cb + p;
                    float gv = acc[mt][nt][e2 * 2 + p];
                    float uv = acc[mt][nt + 2][e2 * 2 + p];
#pragma unroll
                    for (int s = 0; s < 8; s++) {
                        gv += sf[s] * sPg[il * 8 + s];
                        uv += sf[s] * sPu[il * 8 + s];
                    }
                    const float sig = 1.f / (1.f + expf(-gv));
                    const float a = scl * (gv * sig * uv);
                    const float ar = __uint_as_float(f2tf(a));
                    if (p == 0) v.x = ar; else v.y = ar;
                }
                *(float2*)(pa + wn * 16 + nt * 8 + cb) = v;
            }
        }
    }
}

// ---------------------------------------------------------------------------
// G2: y[n0..+128, h0..+128] = sum over (g, k-chunks) act @ Wd^T
// ---------------------------------------------------------------------------
__global__ __launch_bounds__(256, 1) void moe_g2_mma(float* __restrict__ y)
{
    extern __shared__ char smem[];
    const uint32_t sb = s2u(smem);
    const int tid = threadIdx.x, lane = tid & 31;
    const int wn = (tid >> 5) & 3, wm = tid >> 7;
    const int n0 = blockIdx.x * 128, h0 = blockIdx.y * 128;

    const float* srcs[8];
    uint32_t dsts[8];
    int tiles[8];
#pragma unroll
    for (int i = 0; i < 8; i++) {
        const int id = tid + i * 256;
        const int tile = id >> 10, rr = (id >> 3) & 127, cc = id & 7;
        const float* p = (tile == 0) ? g_act + (size_t)(n0 + rr) * IDIM
                                     : g_wdr + (size_t)(h0 + rr) * IDIM;
        srcs[i] = p + cc * 4;
        dsts[i] = sb + tile * TILE_SZ + rr * ROWB + cc * 16;
        tiles[i] = tile;
    }

    float acc[4][4][4];
#pragma unroll
    for (int mt = 0; mt < 4; mt++)
#pragma unroll
        for (int j = 0; j < 4; j++)
#pragma unroll
            for (int e = 0; e < 4; e++) acc[mt][j][e] = 0.f;

    // chunk c -> (g, k): g = c / KCI, k = (c % KCI) * KC
#pragma unroll
    for (int i = 0; i < 8; i++) cpasync16(dsts[i], srcs[i]);
    CP_COMMIT();

    for (int c = 0; c < NC2; c++) {
        const int s = c & 1;
        if (c + 1 < NC2) {
            const int cn = c + 1;
            const int gg = cn / KCI, kk = cn - gg * KCI;
            const size_t offA = ((size_t)gg * N_TOK) * IDIM + (size_t)kk * KC;
            const size_t offB = ((size_t)gg * HDIM) * IDIM + (size_t)kk * KC;
            const uint32_t so = (uint32_t)((1 - s) * STAGE_SZ);
#pragma unroll
            for (int i = 0; i < 8; i++)
                cpasync16(dsts[i] + so, srcs[i] + (tiles[i] == 0 ? offA : offB));
            CP_COMMIT();
            CP_WAIT(1);
        } else {
            CP_WAIT(0);
        }
        __syncthreads();
        mma_stage(sb + s * STAGE_SZ, wm, wn, lane, acc);
        __syncthreads();
    }

    // epilogue: fp32 y
    const int r = lane >> 2, cb = (lane & 3) * 2;
#pragma unroll
    for (int mt = 0; mt < 4; mt++) {
#pragma unroll
        for (int e2 = 0; e2 < 2; e2++) {
            const int n = n0 + wm * 64 + mt * 16 + r + e2 * 8;
            float* row = y + (size_t)n * HDIM + h0 + wn * 32;
#pragma unroll
            for (int nt = 0; nt < 4; nt++) {
                float2 v;
                v.x = acc[mt][nt][e2 * 2];
                v.y = acc[mt][nt][e2 * 2 + 1];
                *(float2*)(row + nt * 8 + cb) = v;
            }
        }
    }
}

// ---------------------------------------------------------------------------
// Launch
// ---------------------------------------------------------------------------
extern "C" void kernel_launch(void* const* d_in, const int* in_sizes, int n_in,
                              void* d_out, int out_size)
{
    const float* x      = (const float*)d_in[0];
    const float* gate_w = (const float*)d_in[1];
    const float* mask_w = (const float*)d_in[2];
    const float* Wg     = (const float*)d_in[3];
    const float* Wu     = (const float*)d_in[4];
    const float* Wd     = (const float*)d_in[5];
    const void*  invmap = (const void*)d_in[6];
    float* y = (float*)d_out;
    (void)in_sizes; (void)n_in; (void)out_size;

    cudaFuncSetAttribute(moe_g1_mma, cudaFuncAttributeMaxDynamicSharedMemorySize, SMEM_TOTAL);
    cudaFuncSetAttribute(moe_g2_mma, cudaFuncAttributeMaxDynamicSharedMemorySize, SMEM_TOTAL);

    float *xr, *wgr, *wur, *wdr;
    cudaGetSymbolAddress((void**)&xr,  g_xr);
    cudaGetSymbolAddress((void**)&wgr, g_wgr);
    cudaGetSymbolAddress((void**)&wur, g_wur);
    cudaGetSymbolAddress((void**)&wdr, g_wdr);

    // prep: tf32 rounding
    tf32_round<<<2048, 256>>>((const float4*)x, (float4*)xr,
                              (int)((size_t)N_TOK * HDIM / 4));
    tf32_round<<<2048, 256>>>((const float4*)Wg, (float4*)wgr,
                              (int)((size_t)NGRP * IDIM * HDIM / 4));
    tf32_round<<<2048, 256>>>((const float4*)Wu, (float4*)wur,
                              (int)((size_t)NGRP * IDIM * HDIM / 4));
    tf32_round<<<2048, 256>>>((const float4*)Wd, (float4*)wdr,
                              (int)((size_t)NGRP * HDIM * IDIM / 4));

    // routing + rank-8 projections (exact fp32)
    moe_route<<<N_TOK, 256>>>(x, gate_w, invmap);
    moe_pproj<<<(NGRP * IDIM) / 8, 256>>>(Wg, Wu, mask_w);

    // G1: gate/up tf32 warp-MMA GEMM + fused epilogue
    dim3 g1grid(N_TOK / 128, IDIM / 64, NGRP);
    moe_g1_mma<<<g1grid, 256, SMEM_TOTAL>>>();

    // G2: down-proj accumulated over groups
    dim3 g2grid(N_TOK / 128, HDIM / 128);
    moe_g2_mma<<<g2grid, 256, SMEM_TOTAL>>>(y);
}

// round 8
// speedup vs baseline: 2.1857x; 1.5473x over previous
#include <cuda_runtime.h>
#include <cuda_bf16.h>
#include <cuda_fp16.h>
#include <math.h>
#include <stdint.h>

// Problem constants
#define N_TOK 2048
#define HDIM  2048
#define IDIM  1408
#define NEXP  64
#define NGRP  8
#define GSZ   8
#define TOPK  8

// GEMM tiling (fp16 operands in smem)
#define KC      32                 // fp16 K elems per chunk (64B rows)
#define ROWB    80                 // smem row stride bytes (64 data + 16 pad)
#define TILE_SZ (128*ROWB)         // 10240 B
#define STAGE_SZ (2*TILE_SZ)       // A,B = 20480 B
#define SMEM_TOTAL (2*STAGE_SZ)    // 40960 B
#define NC1 (HDIM/KC)              // 64
#define KCI (IDIM/KC)              // 44
#define NC2 (NGRP*KCI)             // 352

// ---------------------------------------------------------------------------
// Device global scratch
// ---------------------------------------------------------------------------
__device__ float g_soft[(size_t)N_TOK * NGRP * GSZ];
__device__ float g_scalar[(size_t)N_TOK * NGRP];
__device__ float g_Pg[(size_t)NGRP * IDIM * GSZ];
__device__ float g_Pu[(size_t)NGRP * IDIM * GSZ];

__device__ __half g_xf[(size_t)N_TOK * HDIM];
__device__ __half g_wgf[(size_t)NGRP * IDIM * HDIM];
__device__ __half g_wuf[(size_t)NGRP * IDIM * HDIM];
__device__ __half g_wdf[(size_t)NGRP * HDIM * IDIM];
__device__ __half g_actf[(size_t)NGRP * N_TOK * IDIM];

// ---------------------------------------------------------------------------
// PTX helpers (sm_80-portable only)
// ---------------------------------------------------------------------------
__device__ __forceinline__ uint32_t s2u(const void* p) {
    uint32_t a;
    asm("{ .reg .u64 t; cvta.to.shared.u64 t, %1; cvt.u32.u64 %0, t; }"
        : "=r"(a) : "l"(p));
    return a;
}
__device__ __forceinline__ void cpasync16(uint32_t s, const void* g) {
    asm volatile("cp.async.cg.shared.global [%0], [%1], 16;"
                 :: "r"(s), "l"(g) : "memory");
}
#define CP_COMMIT() asm volatile("cp.async.commit_group;" ::: "memory")
#define CP_WAIT(n)  asm volatile("cp.async.wait_group %0;" :: "n"(n) : "memory")

__device__ __forceinline__ void ldsm4(uint32_t* r, uint32_t addr) {
    asm volatile("ldmatrix.sync.aligned.m8n8.x4.shared.b16 {%0,%1,%2,%3}, [%4];"
                 : "=r"(r[0]), "=r"(r[1]), "=r"(r[2]), "=r"(r[3]) : "r"(addr));
}
// fp16 MMA with fp32 accumulate: D(16x8) += A(16x16) * B(16x8)
__device__ __forceinline__ void mma16816(float* d, const uint32_t* a,
                                         uint32_t b0, uint32_t b1) {
    asm volatile(
        "mma.sync.aligned.m16n8k16.row.col.f32.f16.f16.f32 "
        "{%0,%1,%2,%3}, {%4,%5,%6,%7}, {%8,%9}, {%0,%1,%2,%3};"
        : "+f"(d[0]), "+f"(d[1]), "+f"(d[2]), "+f"(d[3])
        : "r"(a[0]), "r"(a[1]), "r"(a[2]), "r"(a[3]), "r"(b0), "r"(b1));
}

// ---------------------------------------------------------------------------
// Prep: fp32 -> fp16
// ---------------------------------------------------------------------------
__global__ __launch_bounds__(256) void to_half(
    const float4* __restrict__ src, uint2* __restrict__ dst, int n4)
{
    for (int i = blockIdx.x * 256 + threadIdx.x; i < n4; i += gridDim.x * 256) {
        float4 v = src[i];
        __half2 a = __floats2half2_rn(v.x, v.y);
        __half2 b = __floats2half2_rn(v.z, v.w);
        uint2 o;
        o.x = *(uint32_t*)&a;
        o.y = *(uint32_t*)&b;
        dst[i] = o;
    }
}

// ---------------------------------------------------------------------------
// Routing (exact fp32)
// ---------------------------------------------------------------------------
__global__ __launch_bounds__(256) void moe_route(
    const float* __restrict__ x, const float* __restrict__ gate_w,
    const void* __restrict__ inv_map_raw)
{
    __shared__ float xs[HDIM];
    __shared__ float sc[NEXP];
    __shared__ float we[NEXP];

    const int n = blockIdx.x, tid = threadIdx.x;
    const float4* xr4 = (const float4*)(x + (size_t)n * HDIM);
    for (int i = tid; i < HDIM / 4; i += 256) ((float4*)xs)[i] = xr4[i];
    __syncthreads();

    const int warp = tid >> 5, lane = tid & 31;
    float acc[8];
#pragma unroll
    for (int j = 0; j < 8; j++) acc[j] = 0.f;
    const float* gw = gate_w + (size_t)(warp * 8) * HDIM;
    for (int h = lane; h < HDIM; h += 32) {
        float xv = xs[h];
#pragma unroll
        for (int j = 0; j < 8; j++) acc[j] += xv * gw[(size_t)j * HDIM + h];
    }
#pragma unroll
    for (int j = 0; j < 8; j++) {
        float v = acc[j];
#pragma unroll
        for (int o = 16; o > 0; o >>= 1) v += __shfl_down_sync(0xffffffffu, v, o);
        if (lane == 0) sc[warp * 8 + j] = v;
    }
    __syncthreads();

    if (tid == 0) {
        float mx = -1e30f;
        for (int e = 0; e < NEXP; e++) mx = fmaxf(mx, sc[e]);
        float sum = 0.f;
        for (int e = 0; e < NEXP; e++) { float v = expf(sc[e] - mx); sc[e] = v; sum += v; }
        float inv = 1.f / sum;
        for (int e = 0; e < NEXP; e++) { sc[e] *= inv; we[e] = 0.f; }
        for (int k = 0; k < TOPK; k++) {
            int bi = 0; float bv = sc[0];
            for (int e = 1; e < NEXP; e++) if (sc[e] > bv) { bv = sc[e]; bi = e; }
            we[bi] = bv; sc[bi] = -1.f;
        }
    }
    __syncthreads();

    if (tid < NGRP) {
        const int g = tid;
        const int* im32 = (const int*)inv_map_raw;
        const bool is64 = (im32[1] == 0);
        const long long* im64 = (const long long*)inv_map_raw;
        float f[GSZ]; float ss = 0.f;
#pragma unroll
        for (int s = 0; s < GSZ; s++) {
            const int slot = g * GSZ + s;
            const int e = is64 ? (int)im64[slot] : im32[slot];
            f[s] = we[e]; ss += f[s];
        }
        g_scalar[(size_t)n * NGRP + g] = ss;
        float mx = -1e30f;
#pragma unroll
        for (int s = 0; s < GSZ; s++) {
            float v = (f[s] == 0.f) ? -1e9f : f[s];
            f[s] = v; mx = fmaxf(mx, v);
        }
        float es = 0.f;
#pragma unroll
        for (int s = 0; s < GSZ; s++) { float v = expf(f[s] - mx); f[s] = v; es += v; }
        float inv = 1.f / es;
#pragma unroll
        for (int s = 0; s < GSZ; s++)
            g_soft[((size_t)n * NGRP + g) * GSZ + s] = f[s] * inv;
    }
}

// ---------------------------------------------------------------------------
// P projections (fp32 exact)
// ---------------------------------------------------------------------------
__global__ __launch_bounds__(256) void moe_pproj(
    const float* __restrict__ Wg, const float* __restrict__ Wu,
    const float* __restrict__ M)
{
    const int wid = blockIdx.x * 8 + (threadIdx.x >> 5);
    const int lane = threadIdx.x & 31;
    const int g = wid / IDIM, i = wid % IDIM;

    const float* wgr = Wg + ((size_t)g * IDIM + i) * HDIM;
    const float* wur = Wu + ((size_t)g * IDIM + i) * HDIM;
    const float* mg = M + (size_t)g * HDIM * GSZ;

    float ag[8], au[8];
#pragma unroll
    for (int s = 0; s < 8; s++) { ag[s] = 0.f; au[s] = 0.f; }
    for (int h = lane; h < HDIM; h += 32) {
        float wgv = wgr[h], wuv = wur[h];
        const float4* mr = (const float4*)(mg + (size_t)h * GSZ);
        float4 m0 = mr[0], m1 = mr[1];
        ag[0] += wgv * m0.x; ag[1] += wgv * m0.y; ag[2] += wgv * m0.z; ag[3] += wgv * m0.w;
        ag[4] += wgv * m1.x; ag[5] += wgv * m1.y; ag[6] += wgv * m1.z; ag[7] += wgv * m1.w;
        au[0] += wuv * m0.x; au[1] += wuv * m0.y; au[2] += wuv * m0.z; au[3] += wuv * m0.w;
        au[4] += wuv * m1.x; au[5] += wuv * m1.y; au[6] += wuv * m1.z; au[7] += wuv * m1.w;
    }
#pragma unroll
    for (int s = 0; s < 8; s++) {
#pragma unroll
        for (int o = 16; o > 0; o >>= 1) {
            ag[s] += __shfl_down_sync(0xffffffffu, ag[s], o);
            au[s] += __shfl_down_sync(0xffffffffu, au[s], o);
        }
    }
    if (lane == 0) {
        float* pg = &g_Pg[((size_t)g * IDIM + i) * GSZ];
        float* pu = &g_Pu[((size_t)g * IDIM + i) * GSZ];
#pragma unroll
        for (int s = 0; s < 8; s++) { pg[s] = ag[s]; pu[s] = au[s]; }
    }
}

// ---------------------------------------------------------------------------
// fp16 warp-MMA stage: warp tile 64(m) x 32(n), single pass over KC=32.
//   smem stage: [A | B], each 128 rows x 64B (stride 80B).
// ---------------------------------------------------------------------------
__device__ __forceinline__ void mma_stage(uint32_t sbuf, int wm, int wn, int lane,
                                          float acc[4][4][4]) {
    const uint32_t lm = (uint32_t)((lane & 15) * ROWB + (lane >> 4) * 16);
#pragma unroll
    for (int s = 0; s < 2; s++) {                    // k16 steps
        const uint32_t base = sbuf + lm + s * 32;
        uint32_t a[4][4], bx[2][4];
#pragma unroll
        for (int mt = 0; mt < 4; mt++)
            ldsm4(a[mt], base + (wm * 64 + mt * 16) * ROWB);
#pragma unroll
        for (int bt = 0; bt < 2; bt++)
            ldsm4(bx[bt], base + TILE_SZ + (wn * 32 + bt * 16) * ROWB);
#pragma unroll
        for (int mt = 0; mt < 4; mt++)
#pragma unroll
            for (int j = 0; j < 4; j++)
                mma16816(acc[mt][j], a[mt],
                         bx[j >> 1][j & 1], bx[j >> 1][2 + (j & 1)]);
    }
}

// ---------------------------------------------------------------------------
// G1: act[g, n0..+128, i0..+64]. C = 128 tok x 128 cols.
//   C cols per 32-block wn: [0..15]=gate(i0+wn*16+r), [16..31]=up(same i).
//   Warps: wn = wid&3 (4 x 32 cols), wm = wid>>2 (2 x 64 rows).
// ---------------------------------------------------------------------------
__global__ __launch_bounds__(256, 1) void moe_g1_mma()
{
    extern __shared__ char smem[];
    const uint32_t sb = s2u(smem);
    const int tid = threadIdx.x, lane = tid & 31;
    const int wn = (tid >> 5) & 3, wm = tid >> 7;
    const int g = blockIdx.z, i0 = blockIdx.y * 64, n0 = blockIdx.x * 128;

    // loader: 4 x 16B slots per thread per stage
    const __half* srcs[4];
    uint32_t dsts[4];
#pragma unroll
    for (int i = 0; i < 4; i++) {
        const int id = tid + i * 256;
        const int tile = id >> 9, rr = (id >> 2) & 127, cc = id & 3;
        const __half* p;
        if (tile == 0) {
            p = g_xf + (size_t)(n0 + rr) * HDIM;
        } else {
            const int wnr = rr >> 5, within = rr & 31;
            const int irow = i0 + wnr * 16 + (within & 15);
            const __half* base = (within < 16) ? g_wgf : g_wuf;
            p = base + ((size_t)g * IDIM + irow) * HDIM;
        }
        srcs[i] = p + cc * 8;
        dsts[i] = sb + tile * TILE_SZ + rr * ROWB + cc * 16;
    }

    float acc[4][4][4];
#pragma unroll
    for (int mt = 0; mt < 4; mt++)
#pragma unroll
        for (int j = 0; j < 4; j++)
#pragma unroll
            for (int e = 0; e < 4; e++) acc[mt][j][e] = 0.f;

#pragma unroll
    for (int i = 0; i < 4; i++) cpasync16(dsts[i], srcs[i]);
    CP_COMMIT();

    for (int c = 0; c < NC1; c++) {
        const int s = c & 1;
        if (c + 1 < NC1) {
            const int k0 = (c + 1) * KC;
            const uint32_t so = (uint32_t)((1 - s) * STAGE_SZ);
#pragma unroll
            for (int i = 0; i < 4; i++) cpasync16(dsts[i] + so, srcs[i] + k0);
            CP_COMMIT();
            CP_WAIT(1);
        } else {
            CP_WAIT(0);
        }
        __syncthreads();
        mma_stage(sb + s * STAGE_SZ, wm, wn, lane, acc);
        __syncthreads();
    }

    // ---- epilogue: rank-8 correction + silu*up*scalar -> act fp16 ----
    float* sPg = (float*)smem;       // 64 x 8
    float* sPu = sPg + 512;
    float* sSf = sPu + 512;          // 128 x 8
    float* sSc = sSf + 1024;         // 128
    if (tid < 128) {
        ((float4*)sPg)[tid] = ((const float4*)(g_Pg + ((size_t)g * IDIM + i0) * GSZ))[tid];
        ((float4*)sPu)[tid] = ((const float4*)(g_Pu + ((size_t)g * IDIM + i0) * GSZ))[tid];
    }
    {
        const int t = tid >> 1, hf = tid & 1;
        ((float4*)sSf)[tid] =
            *(const float4*)(g_soft + ((size_t)(n0 + t) * NGRP + g) * GSZ + hf * 4);
    }
    if (tid < 128) sSc[tid] = g_scalar[(size_t)(n0 + tid) * NGRP + g];
    __syncthreads();

    const int r = lane >> 2, cb = (lane & 3) * 2;
#pragma unroll
    for (int mt = 0; mt < 4; mt++) {
#pragma unroll
        for (int e2 = 0; e2 < 2; e2++) {
            const int trow = wm * 64 + mt * 16 + r + e2 * 8;
            const int n = n0 + trow;
            float sf[8];
#pragma unroll
            for (int s = 0; s < 8; s++) sf[s] = sSf[trow * 8 + s];
            const float scl = sSc[trow];
            __half* pa = g_actf + ((size_t)g * N_TOK + n) * IDIM + i0;
#pragma unroll
            for (int nt = 0; nt < 2; nt++) {   // gate octet nt, up octet nt+2
                float v0 = 0.f, v1 = 0.f;
#pragma unroll
                for (int p = 0; p < 2; p++) {
                    const int il = wn * 16 + nt * 8 + cb + p;
                    float gv = acc[mt][nt][e2 * 2 + p];
                    float uv = acc[mt][nt + 2][e2 * 2 + p];
#pragma unroll
                    for (int s = 0; s < 8; s++) {
                        gv += sf[s] * sPg[il * 8 + s];
                        uv += sf[s] * sPu[il * 8 + s];
                    }
                    const float sig = 1.f / (1.f + expf(-gv));
                    const float a = scl * (gv * sig * uv);
                    if (p == 0) v0 = a; else v1 = a;
                }
                __half2 hv = __floats2half2_rn(v0, v1);
                *(__half2*)(pa + wn * 16 + nt * 8 + cb) = hv;
            }
        }
    }
}

// ---------------------------------------------------------------------------
// G2: y[n0..+128, h0..+128] = sum over (g, k-chunks) act @ Wd^T
// ---------------------------------------------------------------------------
__global__ __launch_bounds__(256, 1) void moe_g2_mma(float* __restrict__ y)
{
    extern __shared__ char smem[];
    const uint32_t sb = s2u(smem);
    const int tid = threadIdx.x, lane = tid & 31;
    const int wn = (tid >> 5) & 3, wm = tid >> 7;
    const int n0 = blockIdx.x * 128, h0 = blockIdx.y * 128;

    const __half* srcs[4];
    uint32_t dsts[4];
    int tiles[4];
#pragma unroll
    for (int i = 0; i < 4; i++) {
        const int id = tid + i * 256;
        const int tile = id >> 9, rr = (id >> 2) & 127, cc = id & 3;
        const __half* p = (tile == 0) ? g_actf + (size_t)(n0 + rr) * IDIM
                                      : g_wdf + (size_t)(h0 + rr) * IDIM;
        srcs[i] = p + cc * 8;
        dsts[i] = sb + tile * TILE_SZ + rr * ROWB + cc * 16;
        tiles[i] = tile;
    }

    float acc[4][4][4];
#pragma unroll
    for (int mt = 0; mt < 4; mt++)
#pragma unroll
        for (int j = 0; j < 4; j++)
#pragma unroll
            for (int e = 0; e < 4; e++) acc[mt][j][e] = 0.f;

    // chunk c -> (g, k): g = c / KCI, k = (c % KCI) * KC
#pragma unroll
    for (int i = 0; i < 4; i++) cpasync16(dsts[i], srcs[i]);
    CP_COMMIT();

    for (int c = 0; c < NC2; c++) {
        const int s = c & 1;
        if (c + 1 < NC2) {
            const int cn = c + 1;
            const int gg = cn / KCI, kk = cn - gg * KCI;
            const size_t offA = ((size_t)gg * N_TOK) * IDIM + (size_t)kk * KC;
            const size_t offB = ((size_t)gg * HDIM) * IDIM + (size_t)kk * KC;
            const uint32_t so = (uint32_t)((1 - s) * STAGE_SZ);
#pragma unroll
            for (int i = 0; i < 4; i++)
                cpasync16(dsts[i] + so, srcs[i] + (tiles[i] == 0 ? offA : offB));
            CP_COMMIT();
            CP_WAIT(1);
        } else {
            CP_WAIT(0);
        }
        __syncthreads();
        mma_stage(sb + s * STAGE_SZ, wm, wn, lane, acc);
        __syncthreads();
    }

    // epilogue: fp32 y
    const int r = lane >> 2, cb = (lane & 3) * 2;
#pragma unroll
    for (int mt = 0; mt < 4; mt++) {
#pragma unroll
        for (int e2 = 0; e2 < 2; e2++) {
            const int n = n0 + wm * 64 + mt * 16 + r + e2 * 8;
            float* row = y + (size_t)n * HDIM + h0 + wn * 32;
#pragma unroll
            for (int nt = 0; nt < 4; nt++) {
                float2 v;
                v.x = acc[mt][nt][e2 * 2];
                v.y = acc[mt][nt][e2 * 2 + 1];
                *(float2*)(row + nt * 8 + cb) = v;
            }
        }
    }
}

// ---------------------------------------------------------------------------
// Launch
// ---------------------------------------------------------------------------
extern "C" void kernel_launch(void* const* d_in, const int* in_sizes, int n_in,
                              void* d_out, int out_size)
{
    const float* x      = (const float*)d_in[0];
    const float* gate_w = (const float*)d_in[1];
    const float* mask_w = (const float*)d_in[2];
    const float* Wg     = (const float*)d_in[3];
    const float* Wu     = (const float*)d_in[4];
    const float* Wd     = (const float*)d_in[5];
    const void*  invmap = (const void*)d_in[6];
    float* y = (float*)d_out;
    (void)in_sizes; (void)n_in; (void)out_size;

    cudaFuncSetAttribute(moe_g1_mma, cudaFuncAttributeMaxDynamicSharedMemorySize, SMEM_TOTAL);
    cudaFuncSetAttribute(moe_g2_mma, cudaFuncAttributeMaxDynamicSharedMemorySize, SMEM_TOTAL);

    __half *xf, *wgf, *wuf, *wdf;
    cudaGetSymbolAddress((void**)&xf,  g_xf);
    cudaGetSymbolAddress((void**)&wgf, g_wgf);
    cudaGetSymbolAddress((void**)&wuf, g_wuf);
    cudaGetSymbolAddress((void**)&wdf, g_wdf);

    // prep: fp32 -> fp16
    to_half<<<2048, 256>>>((const float4*)x, (uint2*)xf,
                           (int)((size_t)N_TOK * HDIM / 4));
    to_half<<<2048, 256>>>((const float4*)Wg, (uint2*)wgf,
                           (int)((size_t)NGRP * IDIM * HDIM / 4));
    to_half<<<2048, 256>>>((const float4*)Wu, (uint2*)wuf,
                           (int)((size_t)NGRP * IDIM * HDIM / 4));
    to_half<<<2048, 256>>>((const float4*)Wd, (uint2*)wdf,
                           (int)((size_t)NGRP * HDIM * IDIM / 4));

    // routing + rank-8 projections (exact fp32)
    moe_route<<<N_TOK, 256>>>(x, gate_w, invmap);
    moe_pproj<<<(NGRP * IDIM) / 8, 256>>>(Wg, Wu, mask_w);

    // G1: gate/up fp16 warp-MMA GEMM + fused epilogue
    dim3 g1grid(N_TOK / 128, IDIM / 64, NGRP);
    moe_g1_mma<<<g1grid, 256, SMEM_TOTAL>>>();

    // G2: down-proj accumulated over groups
    dim3 g2grid(N_TOK / 128, HDIM / 128);
    moe_g2_mma<<<g2grid, 256, SMEM_TOTAL>>>(y);
}

// round 9
// speedup vs baseline: 2.7249x; 1.2467x over previous
#include <cuda_runtime.h>
#include <cuda_bf16.h>
#include <cuda_fp16.h>
#include <math.h>
#include <stdint.h>

// Problem constants
#define N_TOK 2048
#define HDIM  2048
#define IDIM  1408
#define NEXP  64
#define NGRP  8
#define GSZ   8
#define TOPK  8

// GEMM tiling (fp16 operands in smem)
#define KC      64                 // fp16 K elems per chunk (128B rows)
#define ROWB    144                // smem row stride bytes (128 data + 16 pad)
#define TILE_SZ (128*ROWB)         // 18432 B
#define STAGE_SZ (2*TILE_SZ)       // A,B = 36864 B
#define SMEM_TOTAL (2*STAGE_SZ)    // 73728 B (2 CTAs/SM -> 144KB < 228KB)
#define NC1 (HDIM/KC)              // 32
#define KCI (IDIM/KC)              // 22
#define NC2 (NGRP*KCI)             // 176

// ---------------------------------------------------------------------------
// Device global scratch
// ---------------------------------------------------------------------------
__device__ float g_soft[(size_t)N_TOK * NGRP * GSZ];
__device__ float g_scalar[(size_t)N_TOK * NGRP];
__device__ float g_Pg[(size_t)NGRP * IDIM * GSZ];
__device__ float g_Pu[(size_t)NGRP * IDIM * GSZ];

__device__ __half g_xf[(size_t)N_TOK * HDIM];
__device__ __half g_wgf[(size_t)NGRP * IDIM * HDIM];
__device__ __half g_wuf[(size_t)NGRP * IDIM * HDIM];
__device__ __half g_wdf[(size_t)NGRP * HDIM * IDIM];
__device__ __half g_actf[(size_t)NGRP * N_TOK * IDIM];

// ---------------------------------------------------------------------------
// PTX helpers (sm_80-portable only)
// ---------------------------------------------------------------------------
__device__ __forceinline__ uint32_t s2u(const void* p) {
    uint32_t a;
    asm("{ .reg .u64 t; cvta.to.shared.u64 t, %1; cvt.u32.u64 %0, t; }"
        : "=r"(a) : "l"(p));
    return a;
}
__device__ __forceinline__ void cpasync16(uint32_t s, const void* g) {
    asm volatile("cp.async.cg.shared.global [%0], [%1], 16;"
                 :: "r"(s), "l"(g) : "memory");
}
#define CP_COMMIT() asm volatile("cp.async.commit_group;" ::: "memory")
#define CP_WAIT(n)  asm volatile("cp.async.wait_group %0;" :: "n"(n) : "memory")

__device__ __forceinline__ void ldsm4(uint32_t* r, uint32_t addr) {
    asm volatile("ldmatrix.sync.aligned.m8n8.x4.shared.b16 {%0,%1,%2,%3}, [%4];"
                 : "=r"(r[0]), "=r"(r[1]), "=r"(r[2]), "=r"(r[3]) : "r"(addr));
}
// fp16 MMA with fp32 accumulate: D(16x8) += A(16x16) * B(16x8)
__device__ __forceinline__ void mma16816(float* d, const uint32_t* a,
                                         uint32_t b0, uint32_t b1) {
    asm volatile(
        "mma.sync.aligned.m16n8k16.row.col.f32.f16.f16.f32 "
        "{%0,%1,%2,%3}, {%4,%5,%6,%7}, {%8,%9}, {%0,%1,%2,%3};"
        : "+f"(d[0]), "+f"(d[1]), "+f"(d[2]), "+f"(d[3])
        : "r"(a[0]), "r"(a[1]), "r"(a[2]), "r"(a[3]), "r"(b0), "r"(b1));
}

// ---------------------------------------------------------------------------
// Prep: fp32 -> fp16
// ---------------------------------------------------------------------------
__global__ __launch_bounds__(256) void to_half(
    const float4* __restrict__ src, uint2* __restrict__ dst, int n4)
{
    for (int i = blockIdx.x * 256 + threadIdx.x; i < n4; i += gridDim.x * 256) {
        float4 v = src[i];
        __half2 a = __floats2half2_rn(v.x, v.y);
        __half2 b = __floats2half2_rn(v.z, v.w);
        uint2 o;
        o.x = *(uint32_t*)&a;
        o.y = *(uint32_t*)&b;
        dst[i] = o;
    }
}

// ---------------------------------------------------------------------------
// Routing (exact fp32)
// ---------------------------------------------------------------------------
__global__ __launch_bounds__(256) void moe_route(
    const float* __restrict__ x, const float* __restrict__ gate_w,
    const void* __restrict__ inv_map_raw)
{
    __shared__ float xs[HDIM];
    __shared__ float sc[NEXP];
    __shared__ float we[NEXP];

    const int n = blockIdx.x, tid = threadIdx.x;
    const float4* xr4 = (const float4*)(x + (size_t)n * HDIM);
    for (int i = tid; i < HDIM / 4; i += 256) ((float4*)xs)[i] = xr4[i];
    __syncthreads();

    const int warp = tid >> 5, lane = tid & 31;
    float acc[8];
#pragma unroll
    for (int j = 0; j < 8; j++) acc[j] = 0.f;
    const float* gw = gate_w + (size_t)(warp * 8) * HDIM;
    for (int h = lane; h < HDIM; h += 32) {
        float xv = xs[h];
#pragma unroll
        for (int j = 0; j < 8; j++) acc[j] += xv * gw[(size_t)j * HDIM + h];
    }
#pragma unroll
    for (int j = 0; j < 8; j++) {
        float v = acc[j];
#pragma unroll
        for (int o = 16; o > 0; o >>= 1) v += __shfl_down_sync(0xffffffffu, v, o);
        if (lane == 0) sc[warp * 8 + j] = v;
    }
    __syncthreads();

    if (tid == 0) {
        float mx = -1e30f;
        for (int e = 0; e < NEXP; e++) mx = fmaxf(mx, sc[e]);
        float sum = 0.f;
        for (int e = 0; e < NEXP; e++) { float v = expf(sc[e] - mx); sc[e] = v; sum += v; }
        float inv = 1.f / sum;
        for (int e = 0; e < NEXP; e++) { sc[e] *= inv; we[e] = 0.f; }
        for (int k = 0; k < TOPK; k++) {
            int bi = 0; float bv = sc[0];
            for (int e = 1; e < NEXP; e++) if (sc[e] > bv) { bv = sc[e]; bi = e; }
            we[bi] = bv; sc[bi] = -1.f;
        }
    }
    __syncthreads();

    if (tid < NGRP) {
        const int g = tid;
        const int* im32 = (const int*)inv_map_raw;
        const bool is64 = (im32[1] == 0);
        const long long* im64 = (const long long*)inv_map_raw;
        float f[GSZ]; float ss = 0.f;
#pragma unroll
        for (int s = 0; s < GSZ; s++) {
            const int slot = g * GSZ + s;
            const int e = is64 ? (int)im64[slot] : im32[slot];
            f[s] = we[e]; ss += f[s];
        }
        g_scalar[(size_t)n * NGRP + g] = ss;
        float mx = -1e30f;
#pragma unroll
        for (int s = 0; s < GSZ; s++) {
            float v = (f[s] == 0.f) ? -1e9f : f[s];
            f[s] = v; mx = fmaxf(mx, v);
        }
        float es = 0.f;
#pragma unroll
        for (int s = 0; s < GSZ; s++) { float v = expf(f[s] - mx); f[s] = v; es += v; }
        float inv = 1.f / es;
#pragma unroll
        for (int s = 0; s < GSZ; s++)
            g_soft[((size_t)n * NGRP + g) * GSZ + s] = f[s] * inv;
    }
}

// ---------------------------------------------------------------------------
// P projections (fp32 exact)
// ---------------------------------------------------------------------------
__global__ __launch_bounds__(256) void moe_pproj(
    const float* __restrict__ Wg, const float* __restrict__ Wu,
    const float* __restrict__ M)
{
    const int wid = blockIdx.x * 8 + (threadIdx.x >> 5);
    const int lane = threadIdx.x & 31;
    const int g = wid / IDIM, i = wid % IDIM;

    const float* wgr = Wg + ((size_t)g * IDIM + i) * HDIM;
    const float* wur = Wu + ((size_t)g * IDIM + i) * HDIM;
    const float* mg = M + (size_t)g * HDIM * GSZ;

    float ag[8], au[8];
#pragma unroll
    for (int s = 0; s < 8; s++) { ag[s] = 0.f; au[s] = 0.f; }
    for (int h = lane; h < HDIM; h += 32) {
        float wgv = wgr[h], wuv = wur[h];
        const float4* mr = (const float4*)(mg + (size_t)h * GSZ);
        float4 m0 = mr[0], m1 = mr[1];
        ag[0] += wgv * m0.x; ag[1] += wgv * m0.y; ag[2] += wgv * m0.z; ag[3] += wgv * m0.w;
        ag[4] += wgv * m1.x; ag[5] += wgv * m1.y; ag[6] += wgv * m1.z; ag[7] += wgv * m1.w;
        au[0] += wuv * m0.x; au[1] += wuv * m0.y; au[2] += wuv * m0.z; au[3] += wuv * m0.w;
        au[4] += wuv * m1.x; au[5] += wuv * m1.y; au[6] += wuv * m1.z; au[7] += wuv * m1.w;
    }
#pragma unroll
    for (int s = 0; s < 8; s++) {
#pragma unroll
        for (int o = 16; o > 0; o >>= 1) {
            ag[s] += __shfl_down_sync(0xffffffffu, ag[s], o);
            au[s] += __shfl_down_sync(0xffffffffu, au[s], o);
        }
    }
    if (lane == 0) {
        float* pg = &g_Pg[((size_t)g * IDIM + i) * GSZ];
        float* pu = &g_Pu[((size_t)g * IDIM + i) * GSZ];
#pragma unroll
        for (int s = 0; s < 8; s++) { pg[s] = ag[s]; pu[s] = au[s]; }
    }
}

// ---------------------------------------------------------------------------
// fp16 warp-MMA stage: warp tile 64(m) x 32(n), single pass over KC=64.
//   smem stage: [A | B], each 128 rows x 128B (stride 144B).
//   Per chunk per warp: 24 ldsm + 64 MMA; barriers amortized over 64 MMAs.
// ---------------------------------------------------------------------------
__device__ __forceinline__ void mma_stage(uint32_t sbuf, int wm, int wn, int lane,
                                          float acc[4][4][4]) {
    const uint32_t lm = (uint32_t)((lane & 15) * ROWB + (lane >> 4) * 16);
#pragma unroll
    for (int s = 0; s < 4; s++) {                    // k16 steps
        const uint32_t base = sbuf + lm + s * 32;
        uint32_t a[4][4], bx[2][4];
#pragma unroll
        for (int mt = 0; mt < 4; mt++)
            ldsm4(a[mt], base + (wm * 64 + mt * 16) * ROWB);
#pragma unroll
        for (int bt = 0; bt < 2; bt++)
            ldsm4(bx[bt], base + TILE_SZ + (wn * 32 + bt * 16) * ROWB);
#pragma unroll
        for (int mt = 0; mt < 4; mt++)
#pragma unroll
            for (int j = 0; j < 4; j++)
                mma16816(acc[mt][j], a[mt],
                         bx[j >> 1][j & 1], bx[j >> 1][2 + (j & 1)]);
    }
}

// ---------------------------------------------------------------------------
// G1: act[g, n0..+128, i0..+64]. C = 128 tok x 128 cols.
//   C cols per 32-block wn: [0..15]=gate(i0+wn*16+r), [16..31]=up(same i).
//   Warps: wn = wid&3 (4 x 32 cols), wm = wid>>2 (2 x 64 rows).
// ---------------------------------------------------------------------------
__global__ __launch_bounds__(256, 2) void moe_g1_mma()
{
    extern __shared__ char smem[];
    const uint32_t sb = s2u(smem);
    const int tid = threadIdx.x, lane = tid & 31;
    const int wn = (tid >> 5) & 3, wm = tid >> 7;
    const int g = blockIdx.z, i0 = blockIdx.y * 64, n0 = blockIdx.x * 128;

    // loader: 8 x 16B slots per thread per stage (2 tiles x 128 rows x 8 cc)
    const __half* srcs[8];
    uint32_t dsts[8];
#pragma unroll
    for (int i = 0; i < 8; i++) {
        const int id = tid + i * 256;
        const int tile = id >> 10, rr = (id >> 3) & 127, cc = id & 7;
        const __half* p;
        if (tile == 0) {
            p = g_xf + (size_t)(n0 + rr) * HDIM;
        } else {
            const int wnr = rr >> 5, within = rr & 31;
            const int irow = i0 + wnr * 16 + (within & 15);
            const __half* base = (within < 16) ? g_wgf : g_wuf;
            p = base + ((size_t)g * IDIM + irow) * HDIM;
        }
        srcs[i] = p + cc * 8;
        dsts[i] = sb + tile * TILE_SZ + rr * ROWB + cc * 16;
    }

    float acc[4][4][4];
#pragma unroll
    for (int mt = 0; mt < 4; mt++)
#pragma unroll
        for (int j = 0; j < 4; j++)
#pragma unroll
            for (int e = 0; e < 4; e++) acc[mt][j][e] = 0.f;

#pragma unroll
    for (int i = 0; i < 8; i++) cpasync16(dsts[i], srcs[i]);
    CP_COMMIT();

    for (int c = 0; c < NC1; c++) {
        const int s = c & 1;
        if (c + 1 < NC1) {
            const int k0 = (c + 1) * KC;
            const uint32_t so = (uint32_t)((1 - s) * STAGE_SZ);
#pragma unroll
            for (int i = 0; i < 8; i++) cpasync16(dsts[i] + so, srcs[i] + k0);
            CP_COMMIT();
            CP_WAIT(1);
        } else {
            CP_WAIT(0);
        }
        __syncthreads();
        mma_stage(sb + s * STAGE_SZ, wm, wn, lane, acc);
        __syncthreads();
    }

    // ---- epilogue: rank-8 correction + silu*up*scalar -> act fp16 ----
    float* sPg = (float*)smem;       // 64 x 8
    float* sPu = sPg + 512;
    float* sSf = sPu + 512;          // 128 x 8
    float* sSc = sSf + 1024;         // 128
    if (tid < 128) {
        ((float4*)sPg)[tid] = ((const float4*)(g_Pg + ((size_t)g * IDIM + i0) * GSZ))[tid];
        ((float4*)sPu)[tid] = ((const float4*)(g_Pu + ((size_t)g * IDIM + i0) * GSZ))[tid];
    }
    {
        const int t = tid >> 1, hf = tid & 1;
        ((float4*)sSf)[tid] =
            *(const float4*)(g_soft + ((size_t)(n0 + t) * NGRP + g) * GSZ + hf * 4);
    }
    if (tid < 128) sSc[tid] = g_scalar[(size_t)(n0 + tid) * NGRP + g];
    __syncthreads();

    const int r = lane >> 2, cb = (lane & 3) * 2;
#pragma unroll
    for (int mt = 0; mt < 4; mt++) {
#pragma unroll
        for (int e2 = 0; e2 < 2; e2++) {
            const int trow = wm * 64 + mt * 16 + r + e2 * 8;
            const int n = n0 + trow;
            float sf[8];
#pragma unroll
            for (int s = 0; s < 8; s++) sf[s] = sSf[trow * 8 + s];
            const float scl = sSc[trow];
            __half* pa = g_actf + ((size_t)g * N_TOK + n) * IDIM + i0;
#pragma unroll
            for (int nt = 0; nt < 2; nt++) {   // gate octet nt, up octet nt+2
                float v0 = 0.f, v1 = 0.f;
#pragma unroll
                for (int p = 0; p < 2; p++) {
                    const int il = wn * 16 + nt * 8 + cb + p;
                    float gv = acc[mt][nt][e2 * 2 + p];
                    float uv = acc[mt][nt + 2][e2 * 2 + p];
#pragma unroll
                    for (int s = 0; s < 8; s++) {
                        gv += sf[s] * sPg[il * 8 + s];
                        uv += sf[s] * sPu[il * 8 + s];
                    }
                    const float sig = 1.f / (1.f + expf(-gv));
                    const float a = scl * (gv * sig * uv);
                    if (p == 0) v0 = a; else v1 = a;
                }
                __half2 hv = __floats2half2_rn(v0, v1);
                *(__half2*)(pa + wn * 16 + nt * 8 + cb) = hv;
            }
        }
    }
}

// ---------------------------------------------------------------------------
// G2: y[n0..+128, h0..+128] = sum over (g, k-chunks) act @ Wd^T
// ---------------------------------------------------------------------------
__global__ __launch_bounds__(256, 2) void moe_g2_mma(float* __restrict__ y)
{
    extern __shared__ char smem[];
    const uint32_t sb = s2u(smem);
    const int tid = threadIdx.x, lane = tid & 31;
    const int wn = (tid >> 5) & 3, wm = tid >> 7;
    const int n0 = blockIdx.x * 128, h0 = blockIdx.y * 128;

    const __half* srcs[8];
    uint32_t dsts[8];
    int tiles[8];
#pragma unroll
    for (int i = 0; i < 8; i++) {
        const int id = tid + i * 256;
        const int tile = id >> 10, rr = (id >> 3) & 127, cc = id & 7;
        const __half* p = (tile == 0) ? g_actf + (size_t)(n0 + rr) * IDIM
                                      : g_wdf + (size_t)(h0 + rr) * IDIM;
        srcs[i] = p + cc * 8;
        dsts[i] = sb + tile * TILE_SZ + rr * ROWB + cc * 16;
        tiles[i] = tile;
    }

    float acc[4][4][4];
#pragma unroll
    for (int mt = 0; mt < 4; mt++)
#pragma unroll
        for (int j = 0; j < 4; j++)
#pragma unroll
            for (int e = 0; e < 4; e++) acc[mt][j][e] = 0.f;

    // chunk c -> (g, k): g = c / KCI, k = (c % KCI) * KC
#pragma unroll
    for (int i = 0; i < 8; i++) cpasync16(dsts[i], srcs[i]);
    CP_COMMIT();

    for (int c = 0; c < NC2; c++) {
        const int s = c & 1;
        if (c + 1 < NC2) {
            const int cn = c + 1;
            const int gg = cn / KCI, kk = cn - gg * KCI;
            const size_t offA = ((size_t)gg * N_TOK) * IDIM + (size_t)kk * KC;
            const size_t offB = ((size_t)gg * HDIM) * IDIM + (size_t)kk * KC;
            const uint32_t so = (uint32_t)((1 - s) * STAGE_SZ);
#pragma unroll
            for (int i = 0; i < 8; i++)
                cpasync16(dsts[i] + so, srcs[i] + (tiles[i] == 0 ? offA : offB));
            CP_COMMIT();
            CP_WAIT(1);
        } else {
            CP_WAIT(0);
        }
        __syncthreads();
        mma_stage(sb + s * STAGE_SZ, wm, wn, lane, acc);
        __syncthreads();
    }

    // epilogue: fp32 y
    const int r = lane >> 2, cb = (lane & 3) * 2;
#pragma unroll
    for (int mt = 0; mt < 4; mt++) {
#pragma unroll
        for (int e2 = 0; e2 < 2; e2++) {
            const int n = n0 + wm * 64 + mt * 16 + r + e2 * 8;
            float* row = y + (size_t)n * HDIM + h0 + wn * 32;
#pragma unroll
            for (int nt = 0; nt < 4; nt++) {
                float2 v;
                v.x = acc[mt][nt][e2 * 2];
                v.y = acc[mt][nt][e2 * 2 + 1];
                *(float2*)(row + nt * 8 + cb) = v;
            }
        }
    }
}

// ---------------------------------------------------------------------------
// Launch
// ---------------------------------------------------------------------------
extern "C" void kernel_launch(void* const* d_in, const int* in_sizes, int n_in,
                              void* d_out, int out_size)
{
    const float* x      = (const float*)d_in[0];
    const float* gate_w = (const float*)d_in[1];
    const float* mask_w = (const float*)d_in[2];
    const float* Wg     = (const float*)d_in[3];
    const float* Wu     = (const float*)d_in[4];
    const float* Wd     = (const float*)d_in[5];
    const void*  invmap = (const void*)d_in[6];
    float* y = (float*)d_out;
    (void)in_sizes; (void)n_in; (void)out_size;

    cudaFuncSetAttribute(moe_g1_mma, cudaFuncAttributeMaxDynamicSharedMemorySize, SMEM_TOTAL);
    cudaFuncSetAttribute(moe_g2_mma, cudaFuncAttributeMaxDynamicSharedMemorySize, SMEM_TOTAL);

    __half *xf, *wgf, *wuf, *wdf;
    cudaGetSymbolAddress((void**)&xf,  g_xf);
    cudaGetSymbolAddress((void**)&wgf, g_wgf);
    cudaGetSymbolAddress((void**)&wuf, g_wuf);
    cudaGetSymbolAddress((void**)&wdf, g_wdf);

    // prep: fp32 -> fp16
    to_half<<<2048, 256>>>((const float4*)x, (uint2*)xf,
                           (int)((size_t)N_TOK * HDIM / 4));
    to_half<<<2048, 256>>>((const float4*)Wg, (uint2*)wgf,
                           (int)((size_t)NGRP * IDIM * HDIM / 4));
    to_half<<<2048, 256>>>((const float4*)Wu, (uint2*)wuf,
                           (int)((size_t)NGRP * IDIM * HDIM / 4));
    to_half<<<2048, 256>>>((const float4*)Wd, (uint2*)wdf,
                           (int)((size_t)NGRP * HDIM * IDIM / 4));

    // routing + rank-8 projections (exact fp32)
    moe_route<<<N_TOK, 256>>>(x, gate_w, invmap);
    moe_pproj<<<(NGRP * IDIM) / 8, 256>>>(Wg, Wu, mask_w);

    // G1: gate/up fp16 warp-MMA GEMM + fused epilogue
    dim3 g1grid(N_TOK / 128, IDIM / 64, NGRP);
    moe_g1_mma<<<g1grid, 256, SMEM_TOTAL>>>();

    // G2: down-proj accumulated over groups
    dim3 g2grid(N_TOK / 128, HDIM / 128);
    moe_g2_mma<<<g2grid, 256, SMEM_TOTAL>>>(y);
}

// round 10
// speedup vs baseline: 3.5454x; 1.3011x over previous
#include <cuda_runtime.h>
#include <cuda_bf16.h>
#include <cuda_fp16.h>
#include <math.h>
#include <stdint.h>

// Problem constants
#define N_TOK 2048
#define HDIM  2048
#define IDIM  1408
#define NEXP  64
#define NGRP  8
#define GSZ   8
#define TOPK  8

// GEMM tiling (fp16 operands in smem)
#define KC      64                 // fp16 K elems per chunk (128B rows)
#define ROWB    144                // smem row stride bytes (128 data + 16 pad)
#define TILE_SZ (128*ROWB)         // 18432 B
#define STAGE_SZ (2*TILE_SZ)       // A,B = 36864 B
#define SMEM_TOTAL (2*STAGE_SZ)    // 73728 B (2 CTAs/SM)
#define NC1 (HDIM/KC)              // 32
#define NC2 (IDIM/KC)              // 22 (per-group G2)

// ---------------------------------------------------------------------------
// Device global scratch
// ---------------------------------------------------------------------------
__device__ float g_soft[(size_t)N_TOK * NGRP * GSZ];
__device__ float g_scalar[(size_t)N_TOK * NGRP];
__device__ float g_Pg[(size_t)NGRP * IDIM * GSZ];
__device__ float g_Pu[(size_t)NGRP * IDIM * GSZ];

__device__ int g_list[NGRP][N_TOK];   // compacted active-token lists (sorted)
__device__ int g_cnt[NGRP];

__device__ __half g_xf[(size_t)N_TOK * HDIM];
__device__ __half g_wgf[(size_t)NGRP * IDIM * HDIM];
__device__ __half g_wuf[(size_t)NGRP * IDIM * HDIM];
__device__ __half g_wdf[(size_t)NGRP * HDIM * IDIM];
__device__ __half g_actf[(size_t)NGRP * N_TOK * IDIM];  // compact rows per group

// ---------------------------------------------------------------------------
// PTX helpers (sm_80-portable only)
// ---------------------------------------------------------------------------
__device__ __forceinline__ uint32_t s2u(const void* p) {
    uint32_t a;
    asm("{ .reg .u64 t; cvta.to.shared.u64 t, %1; cvt.u32.u64 %0, t; }"
        : "=r"(a) : "l"(p));
    return a;
}
__device__ __forceinline__ void cpasync16(uint32_t s, const void* g) {
    asm volatile("cp.async.cg.shared.global [%0], [%1], 16;"
                 :: "r"(s), "l"(g) : "memory");
}
#define CP_COMMIT() asm volatile("cp.async.commit_group;" ::: "memory")
#define CP_WAIT(n)  asm volatile("cp.async.wait_group %0;" :: "n"(n) : "memory")

__device__ __forceinline__ void ldsm4(uint32_t* r, uint32_t addr) {
    asm volatile("ldmatrix.sync.aligned.m8n8.x4.shared.b16 {%0,%1,%2,%3}, [%4];"
                 : "=r"(r[0]), "=r"(r[1]), "=r"(r[2]), "=r"(r[3]) : "r"(addr));
}
__device__ __forceinline__ void mma16816(float* d, const uint32_t* a,
                                         uint32_t b0, uint32_t b1) {
    asm volatile(
        "mma.sync.aligned.m16n8k16.row.col.f32.f16.f16.f32 "
        "{%0,%1,%2,%3}, {%4,%5,%6,%7}, {%8,%9}, {%0,%1,%2,%3};"
        : "+f"(d[0]), "+f"(d[1]), "+f"(d[2]), "+f"(d[3])
        : "r"(a[0]), "r"(a[1]), "r"(a[2]), "r"(a[3]), "r"(b0), "r"(b1));
}

// ---------------------------------------------------------------------------
// Prep: fp32 -> fp16
// ---------------------------------------------------------------------------
__global__ __launch_bounds__(256) void to_half(
    const float4* __restrict__ src, uint2* __restrict__ dst, int n4)
{
    for (int i = blockIdx.x * 256 + threadIdx.x; i < n4; i += gridDim.x * 256) {
        float4 v = src[i];
        __half2 a = __floats2half2_rn(v.x, v.y);
        __half2 b = __floats2half2_rn(v.z, v.w);
        uint2 o;
        o.x = *(uint32_t*)&a;
        o.y = *(uint32_t*)&b;
        dst[i] = o;
    }
}

// ---------------------------------------------------------------------------
// Routing (exact fp32)
// ---------------------------------------------------------------------------
__global__ __launch_bounds__(256) void moe_route(
    const float* __restrict__ x, const float* __restrict__ gate_w,
    const void* __restrict__ inv_map_raw)
{
    __shared__ float xs[HDIM];
    __shared__ float sc[NEXP];
    __shared__ float we[NEXP];

    const int n = blockIdx.x, tid = threadIdx.x;
    const float4* xr4 = (const float4*)(x + (size_t)n * HDIM);
    for (int i = tid; i < HDIM / 4; i += 256) ((float4*)xs)[i] = xr4[i];
    __syncthreads();

    const int warp = tid >> 5, lane = tid & 31;
    float acc[8];
#pragma unroll
    for (int j = 0; j < 8; j++) acc[j] = 0.f;
    const float* gw = gate_w + (size_t)(warp * 8) * HDIM;
    for (int h = lane; h < HDIM; h += 32) {
        float xv = xs[h];
#pragma unroll
        for (int j = 0; j < 8; j++) acc[j] += xv * gw[(size_t)j * HDIM + h];
    }
#pragma unroll
    for (int j = 0; j < 8; j++) {
        float v = acc[j];
#pragma unroll
        for (int o = 16; o > 0; o >>= 1) v += __shfl_down_sync(0xffffffffu, v, o);
        if (lane == 0) sc[warp * 8 + j] = v;
    }
    __syncthreads();

    if (tid == 0) {
        float mx = -1e30f;
        for (int e = 0; e < NEXP; e++) mx = fmaxf(mx, sc[e]);
        float sum = 0.f;
        for (int e = 0; e < NEXP; e++) { float v = expf(sc[e] - mx); sc[e] = v; sum += v; }
        float inv = 1.f / sum;
        for (int e = 0; e < NEXP; e++) { sc[e] *= inv; we[e] = 0.f; }
        for (int k = 0; k < TOPK; k++) {
            int bi = 0; float bv = sc[0];
            for (int e = 1; e < NEXP; e++) if (sc[e] > bv) { bv = sc[e]; bi = e; }
            we[bi] = bv; sc[bi] = -1.f;
        }
    }
    __syncthreads();

    if (tid < NGRP) {
        const int g = tid;
        const int* im32 = (const int*)inv_map_raw;
        const bool is64 = (im32[1] == 0);
        const long long* im64 = (const long long*)inv_map_raw;
        float f[GSZ]; float ss = 0.f;
#pragma unroll
        for (int s = 0; s < GSZ; s++) {
            const int slot = g * GSZ + s;
            const int e = is64 ? (int)im64[slot] : im32[slot];
            f[s] = we[e]; ss += f[s];
        }
        g_scalar[(size_t)n * NGRP + g] = ss;
        float mx = -1e30f;
#pragma unroll
        for (int s = 0; s < GSZ; s++) {
            float v = (f[s] == 0.f) ? -1e9f : f[s];
            f[s] = v; mx = fmaxf(mx, v);
        }
        float es = 0.f;
#pragma unroll
        for (int s = 0; s < GSZ; s++) { float v = expf(f[s] - mx); f[s] = v; es += v; }
        float inv = 1.f / es;
#pragma unroll
        for (int s = 0; s < GSZ; s++)
            g_soft[((size_t)n * NGRP + g) * GSZ + s] = f[s] * inv;
    }
}

// ---------------------------------------------------------------------------
// Compaction: per group, deterministic ordered list of active tokens.
// 8 blocks x 256 threads; each thread handles 8 tokens; block scan.
// ---------------------------------------------------------------------------
__global__ __launch_bounds__(256) void moe_compact()
{
    const int g = blockIdx.x, tid = threadIdx.x;
    __shared__ int warpsum[8];

    int flags[8]; int local = 0;
#pragma unroll
    for (int j = 0; j < 8; j++) {
        const int t = tid * 8 + j;
        flags[j] = (g_scalar[(size_t)t * NGRP + g] != 0.f) ? 1 : 0;
        local += flags[j];
    }
    // inclusive warp scan of per-thread sums
    int v = local;
#pragma unroll
    for (int o = 1; o < 32; o <<= 1) {
        int nv = __shfl_up_sync(0xffffffffu, v, o);
        if ((tid & 31) >= o) v += nv;
    }
    if ((tid & 31) == 31) warpsum[tid >> 5] = v;
    __syncthreads();
    if (tid < 8) {
        int w = warpsum[tid];
#pragma unroll
        for (int o = 1; o < 8; o <<= 1) {
            int nw = __shfl_up_sync(0xffu, w, o);
            if (tid >= o) w += nw;
        }
        warpsum[tid] = w;   // inclusive over warps
    }
    __syncthreads();
    int base = v - local + ((tid >= 32) ? warpsum[(tid >> 5) - 1] : 0);
#pragma unroll
    for (int j = 0; j < 8; j++) {
        if (flags[j]) g_list[g][base++] = tid * 8 + j;
    }
    if (tid == 255) g_cnt[g] = base;
}

// ---------------------------------------------------------------------------
// P projections (fp32 exact)
// ---------------------------------------------------------------------------
__global__ __launch_bounds__(256) void moe_pproj(
    const float* __restrict__ Wg, const float* __restrict__ Wu,
    const float* __restrict__ M)
{
    const int wid = blockIdx.x * 8 + (threadIdx.x >> 5);
    const int lane = threadIdx.x & 31;
    const int g = wid / IDIM, i = wid % IDIM;

    const float* wgr = Wg + ((size_t)g * IDIM + i) * HDIM;
    const float* wur = Wu + ((size_t)g * IDIM + i) * HDIM;
    const float* mg = M + (size_t)g * HDIM * GSZ;

    float ag[8], au[8];
#pragma unroll
    for (int s = 0; s < 8; s++) { ag[s] = 0.f; au[s] = 0.f; }
    for (int h = lane; h < HDIM; h += 32) {
        float wgv = wgr[h], wuv = wur[h];
        const float4* mr = (const float4*)(mg + (size_t)h * GSZ);
        float4 m0 = mr[0], m1 = mr[1];
        ag[0] += wgv * m0.x; ag[1] += wgv * m0.y; ag[2] += wgv * m0.z; ag[3] += wgv * m0.w;
        ag[4] += wgv * m1.x; ag[5] += wgv * m1.y; ag[6] += wgv * m1.z; ag[7] += wgv * m1.w;
        au[0] += wuv * m0.x; au[1] += wuv * m0.y; au[2] += wuv * m0.z; au[3] += wuv * m0.w;
        au[4] += wuv * m1.x; au[5] += wuv * m1.y; au[6] += wuv * m1.z; au[7] += wuv * m1.w;
    }
#pragma unroll
    for (int s = 0; s < 8; s++) {
#pragma unroll
        for (int o = 16; o > 0; o >>= 1) {
            ag[s] += __shfl_down_sync(0xffffffffu, ag[s], o);
            au[s] += __shfl_down_sync(0xffffffffu, au[s], o);
        }
    }
    if (lane == 0) {
        float* pg = &g_Pg[((size_t)g * IDIM + i) * GSZ];
        float* pu = &g_Pu[((size_t)g * IDIM + i) * GSZ];
#pragma unroll
        for (int s = 0; s < 8; s++) { pg[s] = ag[s]; pu[s] = au[s]; }
    }
}

// ---------------------------------------------------------------------------
// fp16 warp-MMA stage: warp tile 64(m) x 32(n), KC=64.
// ---------------------------------------------------------------------------
__device__ __forceinline__ void mma_stage(uint32_t sbuf, int wm, int wn, int lane,
                                          float acc[4][4][4]) {
    const uint32_t lm = (uint32_t)((lane & 15) * ROWB + (lane >> 4) * 16);
#pragma unroll
    for (int s = 0; s < 4; s++) {                    // k16 steps
        const uint32_t base = sbuf + lm + s * 32;
        uint32_t a[4][4], bx[2][4];
#pragma unroll
        for (int mt = 0; mt < 4; mt++)
            ldsm4(a[mt], base + (wm * 64 + mt * 16) * ROWB);
#pragma unroll
        for (int bt = 0; bt < 2; bt++)
            ldsm4(bx[bt], base + TILE_SZ + (wn * 32 + bt * 16) * ROWB);
#pragma unroll
        for (int mt = 0; mt < 4; mt++)
#pragma unroll
            for (int j = 0; j < 4; j++)
                mma16816(acc[mt][j], a[mt],
                         bx[j >> 1][j & 1], bx[j >> 1][2 + (j & 1)]);
    }
}

// ---------------------------------------------------------------------------
// G1 (compacted): act_c[g, pos0..+128, i0..+64] for active tokens of group g.
// ---------------------------------------------------------------------------
__global__ __launch_bounds__(256, 2) void moe_g1_mma()
{
    extern __shared__ char smem[];
    const uint32_t sb = s2u(smem);
    const int tid = threadIdx.x, lane = tid & 31;
    const int wn = (tid >> 5) & 3, wm = tid >> 7;
    const int g = blockIdx.z, i0 = blockIdx.y * 64, n0 = blockIdx.x * 128;

    const int cnt = g_cnt[g];
    if (n0 >= cnt) return;

    // loader: 8 x 16B slots per thread per stage
    const __half* srcs[8];
    uint32_t dsts[8];
#pragma unroll
    for (int i = 0; i < 8; i++) {
        const int id = tid + i * 256;
        const int tile = id >> 10, rr = (id >> 3) & 127, cc = id & 7;
        const __half* p;
        if (tile == 0) {
            const int j = n0 + rr;
            const int t = g_list[g][j < cnt ? j : cnt - 1];
            p = g_xf + (size_t)t * HDIM;
        } else {
            const int wnr = rr >> 5, within = rr & 31;
            const int irow = i0 + wnr * 16 + (within & 15);
            const __half* base = (within < 16) ? g_wgf : g_wuf;
            p = base + ((size_t)g * IDIM + irow) * HDIM;
        }
        srcs[i] = p + cc * 8;
        dsts[i] = sb + tile * TILE_SZ + rr * ROWB + cc * 16;
    }

    float acc[4][4][4];
#pragma unroll
    for (int mt = 0; mt < 4; mt++)
#pragma unroll
        for (int j = 0; j < 4; j++)
#pragma unroll
            for (int e = 0; e < 4; e++) acc[mt][j][e] = 0.f;

#pragma unroll
    for (int i = 0; i < 8; i++) cpasync16(dsts[i], srcs[i]);
    CP_COMMIT();

    for (int c = 0; c < NC1; c++) {
        const int s = c & 1;
        if (c + 1 < NC1) {
            const int k0 = (c + 1) * KC;
            const uint32_t so = (uint32_t)((1 - s) * STAGE_SZ);
#pragma unroll
            for (int i = 0; i < 8; i++) cpasync16(dsts[i] + so, srcs[i] + k0);
            CP_COMMIT();
            CP_WAIT(1);
        } else {
            CP_WAIT(0);
        }
        __syncthreads();
        mma_stage(sb + s * STAGE_SZ, wm, wn, lane, acc);
        __syncthreads();
    }

    // ---- epilogue: correction + silu*up*scalar -> compact act fp16 ----
    float* sPg = (float*)smem;       // 64 x 8
    float* sPu = sPg + 512;
    float* sSf = sPu + 512;          // 128 x 8
    float* sSc = sSf + 1024;         // 128
    if (tid < 128) {
        ((float4*)sPg)[tid] = ((const float4*)(g_Pg + ((size_t)g * IDIM + i0) * GSZ))[tid];
        ((float4*)sPu)[tid] = ((const float4*)(g_Pu + ((size_t)g * IDIM + i0) * GSZ))[tid];
    }
    {
        const int rrow = tid >> 1, hf = tid & 1;
        const int j = n0 + rrow;
        const int t = g_list[g][j < cnt ? j : cnt - 1];
        ((float4*)sSf)[tid] =
            *(const float4*)(g_soft + ((size_t)t * NGRP + g) * GSZ + hf * 4);
        if (hf == 0) sSc[rrow] = g_scalar[(size_t)t * NGRP + g];
    }
    __syncthreads();

    const int r = lane >> 2, cb = (lane & 3) * 2;
#pragma unroll
    for (int mt = 0; mt < 4; mt++) {
#pragma unroll
        for (int e2 = 0; e2 < 2; e2++) {
            const int trow = wm * 64 + mt * 16 + r + e2 * 8;
            if (n0 + trow >= cnt) continue;
            float sf[8];
#pragma unroll
            for (int s = 0; s < 8; s++) sf[s] = sSf[trow * 8 + s];
            const float scl = sSc[trow];
            __half* pa = g_actf + ((size_t)g * N_TOK + n0 + trow) * IDIM + i0;
#pragma unroll
            for (int nt = 0; nt < 2; nt++) {
                float v0 = 0.f, v1 = 0.f;
#pragma unroll
                for (int p = 0; p < 2; p++) {
                    const int il = wn * 16 + nt * 8 + cb + p;
                    float gv = acc[mt][nt][e2 * 2 + p];
                    float uv = acc[mt][nt + 2][e2 * 2 + p];
#pragma unroll
                    for (int s = 0; s < 8; s++) {
                        gv += sf[s] * sPg[il * 8 + s];
                        uv += sf[s] * sPu[il * 8 + s];
                    }
                    const float sig = 1.f / (1.f + expf(-gv));
                    const float a = scl * (gv * sig * uv);
                    if (p == 0) v0 = a; else v1 = a;
                }
                __half2 hv = __floats2half2_rn(v0, v1);
                *(__half2*)(pa + wn * 16 + nt * 8 + cb) = hv;
            }
        }
    }
}

// ---------------------------------------------------------------------------
// G2 (per-group, compacted): y[t, h0..+128] += act_c[g] @ Wd_g^T rows,
// scattered via atomicAdd (y pre-zeroed).
// ---------------------------------------------------------------------------
__global__ __launch_bounds__(256, 2) void moe_g2_mma(float* __restrict__ y)
{
    extern __shared__ char smem[];
    const uint32_t sb = s2u(smem);
    const int tid = threadIdx.x, lane = tid & 31;
    const int wn = (tid >> 5) & 3, wm = tid >> 7;
    const int g = blockIdx.z, n0 = blockIdx.x * 128, h0 = blockIdx.y * 128;

    const int cnt = g_cnt[g];
    if (n0 >= cnt) return;

    const __half* srcs[8];
    uint32_t dsts[8];
#pragma unroll
    for (int i = 0; i < 8; i++) {
        const int id = tid + i * 256;
        const int tile = id >> 10, rr = (id >> 3) & 127, cc = id & 7;
        const __half* p;
        if (tile == 0) {
            const int j = n0 + rr;
            const int jc = j < cnt ? j : cnt - 1;
            p = g_actf + ((size_t)g * N_TOK + jc) * IDIM;
        } else {
            p = g_wdf + ((size_t)g * HDIM + h0 + rr) * IDIM;
        }
        srcs[i] = p + cc * 8;
        dsts[i] = sb + tile * TILE_SZ + rr * ROWB + cc * 16;
    }

    float acc[4][4][4];
#pragma unroll
    for (int mt = 0; mt < 4; mt++)
#pragma unroll
        for (int j = 0; j < 4; j++)
#pragma unroll
            for (int e = 0; e < 4; e++) acc[mt][j][e] = 0.f;

#pragma unroll
    for (int i = 0; i < 8; i++) cpasync16(dsts[i], srcs[i]);
    CP_COMMIT();

    for (int c = 0; c < NC2; c++) {
        const int s = c & 1;
        if (c + 1 < NC2) {
            const int k0 = (c + 1) * KC;
            const uint32_t so = (uint32_t)((1 - s) * STAGE_SZ);
#pragma unroll
            for (int i = 0; i < 8; i++) cpasync16(dsts[i] + so, srcs[i] + k0);
            CP_COMMIT();
            CP_WAIT(1);
        } else {
            CP_WAIT(0);
        }
        __syncthreads();
        mma_stage(sb + s * STAGE_SZ, wm, wn, lane, acc);
        __syncthreads();
    }

    // epilogue: scatter-add into y
    const int r = lane >> 2, cb = (lane & 3) * 2;
#pragma unroll
    for (int mt = 0; mt < 4; mt++) {
#pragma unroll
        for (int e2 = 0; e2 < 2; e2++) {
            const int row = wm * 64 + mt * 16 + r + e2 * 8;
            if (n0 + row >= cnt) continue;
            const int t = g_list[g][n0 + row];
            float* yrow = y + (size_t)t * HDIM + h0 + wn * 32;
#pragma unroll
            for (int nt = 0; nt < 4; nt++) {
                atomicAdd(yrow + nt * 8 + cb,     acc[mt][nt][e2 * 2]);
                atomicAdd(yrow + nt * 8 + cb + 1, acc[mt][nt][e2 * 2 + 1]);
            }
        }
    }
}

// ---------------------------------------------------------------------------
// Launch
// ---------------------------------------------------------------------------
extern "C" void kernel_launch(void* const* d_in, const int* in_sizes, int n_in,
                              void* d_out, int out_size)
{
    const float* x      = (const float*)d_in[0];
    const float* gate_w = (const float*)d_in[1];
    const float* mask_w = (const float*)d_in[2];
    const float* Wg     = (const float*)d_in[3];
    const float* Wu     = (const float*)d_in[4];
    const float* Wd     = (const float*)d_in[5];
    const void*  invmap = (const void*)d_in[6];
    float* y = (float*)d_out;
    (void)in_sizes; (void)n_in;

    cudaFuncSetAttribute(moe_g1_mma, cudaFuncAttributeMaxDynamicSharedMemorySize, SMEM_TOTAL);
    cudaFuncSetAttribute(moe_g2_mma, cudaFuncAttributeMaxDynamicSharedMemorySize, SMEM_TOTAL);

    __half *xf, *wgf, *wuf, *wdf;
    cudaGetSymbolAddress((void**)&xf,  g_xf);
    cudaGetSymbolAddress((void**)&wgf, g_wgf);
    cudaGetSymbolAddress((void**)&wuf, g_wuf);
    cudaGetSymbolAddress((void**)&wdf, g_wdf);

    // prep: fp32 -> fp16
    to_half<<<2048, 256>>>((const float4*)x, (uint2*)xf,
                           (int)((size_t)N_TOK * HDIM / 4));
    to_half<<<2048, 256>>>((const float4*)Wg, (uint2*)wgf,
                           (int)((size_t)NGRP * IDIM * HDIM / 4));
    to_half<<<2048, 256>>>((const float4*)Wu, (uint2*)wuf,
                           (int)((size_t)NGRP * IDIM * HDIM / 4));
    to_half<<<2048, 256>>>((const float4*)Wd, (uint2*)wdf,
                           (int)((size_t)NGRP * HDIM * IDIM / 4));

    // routing -> compaction ; rank-8 projections
    moe_route<<<N_TOK, 256>>>(x, gate_w, invmap);
    moe_compact<<<NGRP, 256>>>();
    moe_pproj<<<(NGRP * IDIM) / 8, 256>>>(Wg, Wu, mask_w);

    // zero y (G2 scatter-adds)
    cudaMemsetAsync(y, 0, (size_t)out_size * sizeof(float));

    // G1: compacted gate/up GEMM + fused epilogue
    dim3 g1grid(N_TOK / 128, IDIM / 64, NGRP);
    moe_g1_mma<<<g1grid, 256, SMEM_TOTAL>>>();

    // G2: per-group down-proj, scatter-add into y
    dim3 g2grid(N_TOK / 128, HDIM / 128, NGRP);
    moe_g2_mma<<<g2grid, 256, SMEM_TOTAL>>>(y);
}

// round 11
// speedup vs baseline: 3.6437x; 1.0277x over previous
#include <cuda_runtime.h>
#include <cuda_bf16.h>
#include <cuda_fp16.h>
#include <math.h>
#include <stdint.h>

// Problem constants
#define N_TOK 2048
#define HDIM  2048
#define IDIM  1408
#define NEXP  64
#define NGRP  8
#define GSZ   8
#define TOPK  8

// GEMM tiling (fp16 operands in smem)
#define KC      64                 // fp16 K elems per chunk (128B rows)
#define ROWB    144                // smem row stride bytes (128 data + 16 pad)
#define TILE_SZ (128*ROWB)         // 18432 B
#define STAGE_SZ (2*TILE_SZ)       // A,B = 36864 B
#define NSTAGE  3
#define SMEM_TOTAL (NSTAGE*STAGE_SZ)  // 110592 B (2 CTAs/SM -> 221KB < 228KB)
#define NC1 (HDIM/KC)              // 32
#define NC2 (IDIM/KC)              // 22 (per-group G2)

// ---------------------------------------------------------------------------
// Device global scratch
// ---------------------------------------------------------------------------
__device__ float g_soft[(size_t)N_TOK * NGRP * GSZ];
__device__ float g_scalar[(size_t)N_TOK * NGRP];
__device__ float g_Pg[(size_t)NGRP * IDIM * GSZ];
__device__ float g_Pu[(size_t)NGRP * IDIM * GSZ];

__device__ int g_list[NGRP][N_TOK];   // compacted active-token lists (sorted)
__device__ int g_cnt[NGRP];

__device__ __half g_xf[(size_t)N_TOK * HDIM];
__device__ __half g_wgf[(size_t)NGRP * IDIM * HDIM];
__device__ __half g_wuf[(size_t)NGRP * IDIM * HDIM];
__device__ __half g_wdf[(size_t)NGRP * HDIM * IDIM];
__device__ __half g_actf[(size_t)NGRP * N_TOK * IDIM];  // compact rows per group

// ---------------------------------------------------------------------------
// PTX helpers (sm_80-portable only)
// ---------------------------------------------------------------------------
__device__ __forceinline__ uint32_t s2u(const void* p) {
    uint32_t a;
    asm("{ .reg .u64 t; cvta.to.shared.u64 t, %1; cvt.u32.u64 %0, t; }"
        : "=r"(a) : "l"(p));
    return a;
}
__device__ __forceinline__ void cpasync16(uint32_t s, const void* g) {
    asm volatile("cp.async.cg.shared.global [%0], [%1], 16;"
                 :: "r"(s), "l"(g) : "memory");
}
#define CP_COMMIT() asm volatile("cp.async.commit_group;" ::: "memory")
#define CP_WAIT(n)  asm volatile("cp.async.wait_group %0;" :: "n"(n) : "memory")

__device__ __forceinline__ void ldsm4(uint32_t* r, uint32_t addr) {
    asm volatile("ldmatrix.sync.aligned.m8n8.x4.shared.b16 {%0,%1,%2,%3}, [%4];"
                 : "=r"(r[0]), "=r"(r[1]), "=r"(r[2]), "=r"(r[3]) : "r"(addr));
}
__device__ __forceinline__ void mma16816(float* d, const uint32_t* a,
                                         uint32_t b0, uint32_t b1) {
    asm volatile(
        "mma.sync.aligned.m16n8k16.row.col.f32.f16.f16.f32 "
        "{%0,%1,%2,%3}, {%4,%5,%6,%7}, {%8,%9}, {%0,%1,%2,%3};"
        : "+f"(d[0]), "+f"(d[1]), "+f"(d[2]), "+f"(d[3])
        : "r"(a[0]), "r"(a[1]), "r"(a[2]), "r"(a[3]), "r"(b0), "r"(b1));
}

// ---------------------------------------------------------------------------
// Prep: fp32 -> fp16 (only Wd needs a standalone pass now)
// ---------------------------------------------------------------------------
__global__ __launch_bounds__(256) void to_half(
    const float4* __restrict__ src, uint2* __restrict__ dst, int n4)
{
    for (int i = blockIdx.x * 256 + threadIdx.x; i < n4; i += gridDim.x * 256) {
        float4 v = src[i];
        __half2 a = __floats2half2_rn(v.x, v.y);
        __half2 b = __floats2half2_rn(v.z, v.w);
        uint2 o;
        o.x = *(uint32_t*)&a;
        o.y = *(uint32_t*)&b;
        dst[i] = o;
    }
}

// ---------------------------------------------------------------------------
// Routing (exact fp32) + fused x->fp16 conversion
// ---------------------------------------------------------------------------
__global__ __launch_bounds__(256) void moe_route(
    const float* __restrict__ x, const float* __restrict__ gate_w,
    const void* __restrict__ inv_map_raw)
{
    __shared__ float xs[HDIM];
    __shared__ float sc[NEXP];
    __shared__ float we[NEXP];

    const int n = blockIdx.x, tid = threadIdx.x;
    const float4* xr4 = (const float4*)(x + (size_t)n * HDIM);
    for (int i = tid; i < HDIM / 4; i += 256) ((float4*)xs)[i] = xr4[i];
    __syncthreads();

    // fused: write fp16 copy of this token's row
    {
        __half2* xo = (__half2*)(g_xf + (size_t)n * HDIM);
#pragma unroll
        for (int i = tid; i < HDIM / 2; i += 256)
            xo[i] = __floats2half2_rn(xs[2 * i], xs[2 * i + 1]);
    }

    const int warp = tid >> 5, lane = tid & 31;
    float acc[8];
#pragma unroll
    for (int j = 0; j < 8; j++) acc[j] = 0.f;
    const float* gw = gate_w + (size_t)(warp * 8) * HDIM;
    for (int h = lane; h < HDIM; h += 32) {
        float xv = xs[h];
#pragma unroll
        for (int j = 0; j < 8; j++) acc[j] += xv * gw[(size_t)j * HDIM + h];
    }
#pragma unroll
    for (int j = 0; j < 8; j++) {
        float v = acc[j];
#pragma unroll
        for (int o = 16; o > 0; o >>= 1) v += __shfl_down_sync(0xffffffffu, v, o);
        if (lane == 0) sc[warp * 8 + j] = v;
    }
    __syncthreads();

    if (tid == 0) {
        float mx = -1e30f;
        for (int e = 0; e < NEXP; e++) mx = fmaxf(mx, sc[e]);
        float sum = 0.f;
        for (int e = 0; e < NEXP; e++) { float v = expf(sc[e] - mx); sc[e] = v; sum += v; }
        float inv = 1.f / sum;
        for (int e = 0; e < NEXP; e++) { sc[e] *= inv; we[e] = 0.f; }
        for (int k = 0; k < TOPK; k++) {
            int bi = 0; float bv = sc[0];
            for (int e = 1; e < NEXP; e++) if (sc[e] > bv) { bv = sc[e]; bi = e; }
            we[bi] = bv; sc[bi] = -1.f;
        }
    }
    __syncthreads();

    if (tid < NGRP) {
        const int g = tid;
        const int* im32 = (const int*)inv_map_raw;
        const bool is64 = (im32[1] == 0);
        const long long* im64 = (const long long*)inv_map_raw;
        float f[GSZ]; float ss = 0.f;
#pragma unroll
        for (int s = 0; s < GSZ; s++) {
            const int slot = g * GSZ + s;
            const int e = is64 ? (int)im64[slot] : im32[slot];
            f[s] = we[e]; ss += f[s];
        }
        g_scalar[(size_t)n * NGRP + g] = ss;
        float mx = -1e30f;
#pragma unroll
        for (int s = 0; s < GSZ; s++) {
            float v = (f[s] == 0.f) ? -1e9f : f[s];
            f[s] = v; mx = fmaxf(mx, v);
        }
        float es = 0.f;
#pragma unroll
        for (int s = 0; s < GSZ; s++) { float v = expf(f[s] - mx); f[s] = v; es += v; }
        float inv = 1.f / es;
#pragma unroll
        for (int s = 0; s < GSZ; s++)
            g_soft[((size_t)n * NGRP + g) * GSZ + s] = f[s] * inv;
    }
}

// ---------------------------------------------------------------------------
// Compaction: per group, deterministic ordered list of active tokens.
// ---------------------------------------------------------------------------
__global__ __launch_bounds__(256) void moe_compact()
{
    const int g = blockIdx.x, tid = threadIdx.x;
    __shared__ int warpsum[8];

    int flags[8]; int local = 0;
#pragma unroll
    for (int j = 0; j < 8; j++) {
        const int t = tid * 8 + j;
        flags[j] = (g_scalar[(size_t)t * NGRP + g] != 0.f) ? 1 : 0;
        local += flags[j];
    }
    int v = local;
#pragma unroll
    for (int o = 1; o < 32; o <<= 1) {
        int nv = __shfl_up_sync(0xffffffffu, v, o);
        if ((tid & 31) >= o) v += nv;
    }
    if ((tid & 31) == 31) warpsum[tid >> 5] = v;
    __syncthreads();
    if (tid < 8) {
        int w = warpsum[tid];
#pragma unroll
        for (int o = 1; o < 8; o <<= 1) {
            int nw = __shfl_up_sync(0xffu, w, o);
            if (tid >= o) w += nw;
        }
        warpsum[tid] = w;
    }
    __syncthreads();
    int base = v - local + ((tid >= 32) ? warpsum[(tid >> 5) - 1] : 0);
#pragma unroll
    for (int j = 0; j < 8; j++) {
        if (flags[j]) g_list[g][base++] = tid * 8 + j;
    }
    if (tid == 255) g_cnt[g] = base;
}

// ---------------------------------------------------------------------------
// P projections (fp32 exact) + fused Wg/Wu -> fp16 conversion
// ---------------------------------------------------------------------------
__global__ __launch_bounds__(256) void moe_pproj(
    const float* __restrict__ Wg, const float* __restrict__ Wu,
    const float* __restrict__ M)
{
    const int wid = blockIdx.x * 8 + (threadIdx.x >> 5);
    const int lane = threadIdx.x & 31;
    const int g = wid / IDIM, i = wid % IDIM;

    const size_t rowoff = ((size_t)g * IDIM + i) * HDIM;
    const float* wgr = Wg + rowoff;
    const float* wur = Wu + rowoff;
    const float* mg = M + (size_t)g * HDIM * GSZ;
    __half* wgo = g_wgf + rowoff;
    __half* wuo = g_wuf + rowoff;

    float ag[8], au[8];
#pragma unroll
    for (int s = 0; s < 8; s++) { ag[s] = 0.f; au[s] = 0.f; }
    for (int h = lane; h < HDIM; h += 32) {
        float wgv = wgr[h], wuv = wur[h];
        wgo[h] = __float2half_rn(wgv);           // fused fp16 write
        wuo[h] = __float2half_rn(wuv);
        const float4* mr = (const float4*)(mg + (size_t)h * GSZ);
        float4 m0 = mr[0], m1 = mr[1];
        ag[0] += wgv * m0.x; ag[1] += wgv * m0.y; ag[2] += wgv * m0.z; ag[3] += wgv * m0.w;
        ag[4] += wgv * m1.x; ag[5] += wgv * m1.y; ag[6] += wgv * m1.z; ag[7] += wgv * m1.w;
        au[0] += wuv * m0.x; au[1] += wuv * m0.y; au[2] += wuv * m0.z; au[3] += wuv * m0.w;
        au[4] += wuv * m1.x; au[5] += wuv * m1.y; au[6] += wuv * m1.z; au[7] += wuv * m1.w;
    }
#pragma unroll
    for (int s = 0; s < 8; s++) {
#pragma unroll
        for (int o = 16; o > 0; o >>= 1) {
            ag[s] += __shfl_down_sync(0xffffffffu, ag[s], o);
            au[s] += __shfl_down_sync(0xffffffffu, au[s], o);
        }
    }
    if (lane == 0) {
        float* pg = &g_Pg[((size_t)g * IDIM + i) * GSZ];
        float* pu = &g_Pu[((size_t)g * IDIM + i) * GSZ];
#pragma unroll
        for (int s = 0; s < 8; s++) { pg[s] = ag[s]; pu[s] = au[s]; }
    }
}

// ---------------------------------------------------------------------------
// fp16 warp-MMA stage: warp tile 64(m) x 32(n), KC=64.
// ---------------------------------------------------------------------------
__device__ __forceinline__ void mma_stage(uint32_t sbuf, int wm, int wn, int lane,
                                          float acc[4][4][4]) {
    const uint32_t lm = (uint32_t)((lane & 15) * ROWB + (lane >> 4) * 16);
#pragma unroll
    for (int s = 0; s < 4; s++) {                    // k16 steps
        const uint32_t base = sbuf + lm + s * 32;
        uint32_t a[4][4], bx[2][4];
#pragma unroll
        for (int mt = 0; mt < 4; mt++)
            ldsm4(a[mt], base + (wm * 64 + mt * 16) * ROWB);
#pragma unroll
        for (int bt = 0; bt < 2; bt++)
            ldsm4(bx[bt], base + TILE_SZ + (wn * 32 + bt * 16) * ROWB);
#pragma unroll
        for (int mt = 0; mt < 4; mt++)
#pragma unroll
            for (int j = 0; j < 4; j++)
                mma16816(acc[mt][j], a[mt],
                         bx[j >> 1][j & 1], bx[j >> 1][2 + (j & 1)]);
    }
}

// ---------------------------------------------------------------------------
// G1 (compacted): act_c[g, pos0..+128, i0..+64] for active tokens of group g.
// 3-stage cp.async ring, single __syncthreads per chunk.
// ---------------------------------------------------------------------------
__global__ __launch_bounds__(256, 2) void moe_g1_mma()
{
    extern __shared__ char smem[];
    const uint32_t sb = s2u(smem);
    const int tid = threadIdx.x, lane = tid & 31;
    const int wn = (tid >> 5) & 3, wm = tid >> 7;
    const int g = blockIdx.z, i0 = blockIdx.y * 64, n0 = blockIdx.x * 128;

    const int cnt = g_cnt[g];
    if (n0 >= cnt) return;

    const __half* srcs[8];
    uint32_t dsts[8];
#pragma unroll
    for (int i = 0; i < 8; i++) {
        const int id = tid + i * 256;
        const int tile = id >> 10, rr = (id >> 3) & 127, cc = id & 7;
        const __half* p;
        if (tile == 0) {
            const int j = n0 + rr;
            const int t = g_list[g][j < cnt ? j : cnt - 1];
            p = g_xf + (size_t)t * HDIM;
        } else {
            const int wnr = rr >> 5, within = rr & 31;
            const int irow = i0 + wnr * 16 + (within & 15);
            const __half* base = (within < 16) ? g_wgf : g_wuf;
            p = base + ((size_t)g * IDIM + irow) * HDIM;
        }
        srcs[i] = p + cc * 8;
        dsts[i] = sb + tile * TILE_SZ + rr * ROWB + cc * 16;
    }

    float acc[4][4][4];
#pragma unroll
    for (int mt = 0; mt < 4; mt++)
#pragma unroll
        for (int j = 0; j < 4; j++)
#pragma unroll
            for (int e = 0; e < 4; e++) acc[mt][j][e] = 0.f;

    // prologue: stages 0,1
#pragma unroll
    for (int i = 0; i < 8; i++) cpasync16(dsts[i], srcs[i]);
    CP_COMMIT();
#pragma unroll
    for (int i = 0; i < 8; i++) cpasync16(dsts[i] + STAGE_SZ, srcs[i] + KC);
    CP_COMMIT();

    for (int c = 0; c < NC1; c++) {
        CP_WAIT(1);
        __syncthreads();
        mma_stage(sb + (uint32_t)((c % NSTAGE) * STAGE_SZ), wm, wn, lane, acc);
        if (c + 2 < NC1) {
            const int k0 = (c + 2) * KC;
            const uint32_t so = (uint32_t)(((c + 2) % NSTAGE) * STAGE_SZ);
#pragma unroll
            for (int i = 0; i < 8; i++) cpasync16(dsts[i] + so, srcs[i] + k0);
        }
        CP_COMMIT();
    }

    // ---- epilogue: correction + silu*up*scalar -> compact act fp16 ----
    __syncthreads();
    float* sPg = (float*)smem;       // 64 x 8
    float* sPu = sPg + 512;
    float* sSf = sPu + 512;          // 128 x 8
    float* sSc = sSf + 1024;         // 128
    if (tid < 128) {
        ((float4*)sPg)[tid] = ((const float4*)(g_Pg + ((size_t)g * IDIM + i0) * GSZ))[tid];
        ((float4*)sPu)[tid] = ((const float4*)(g_Pu + ((size_t)g * IDIM + i0) * GSZ))[tid];
    }
    {
        const int rrow = tid >> 1, hf = tid & 1;
        const int j = n0 + rrow;
        const int t = g_list[g][j < cnt ? j : cnt - 1];
        ((float4*)sSf)[tid] =
            *(const float4*)(g_soft + ((size_t)t * NGRP + g) * GSZ + hf * 4);
        if (hf == 0) sSc[rrow] = g_scalar[(size_t)t * NGRP + g];
    }
    __syncthreads();

    const int r = lane >> 2, cb = (lane & 3) * 2;
#pragma unroll
    for (int mt = 0; mt < 4; mt++) {
#pragma unroll
        for (int e2 = 0; e2 < 2; e2++) {
            const int trow = wm * 64 + mt * 16 + r + e2 * 8;
            if (n0 + trow >= cnt) continue;
            float sf[8];
#pragma unroll
            for (int s = 0; s < 8; s++) sf[s] = sSf[trow * 8 + s];
            const float scl = sSc[trow];
            __half* pa = g_actf + ((size_t)g * N_TOK + n0 + trow) * IDIM + i0;
#pragma unroll
            for (int nt = 0; nt < 2; nt++) {
                float v0 = 0.f, v1 = 0.f;
#pragma unroll
                for (int p = 0; p < 2; p++) {
                    const int il = wn * 16 + nt * 8 + cb + p;
                    float gv = acc[mt][nt][e2 * 2 + p];
                    float uv = acc[mt][nt + 2][e2 * 2 + p];
#pragma unroll
                    for (int s = 0; s < 8; s++) {
                        gv += sf[s] * sPg[il * 8 + s];
                        uv += sf[s] * sPu[il * 8 + s];
                    }
                    const float sig = 1.f / (1.f + expf(-gv));
                    const float a = scl * (gv * sig * uv);
                    if (p == 0) v0 = a; else v1 = a;
                }
                __half2 hv = __floats2half2_rn(v0, v1);
                *(__half2*)(pa + wn * 16 + nt * 8 + cb) = hv;
            }
        }
    }
}

// ---------------------------------------------------------------------------
// G2 (per-group, compacted): y[t, h0..+128] += act_c[g] @ Wd_g^T, atomicAdd.
// 3-stage ring, single sync per chunk.
// ---------------------------------------------------------------------------
__global__ __launch_bounds__(256, 2) void moe_g2_mma(float* __restrict__ y)
{
    extern __shared__ char smem[];
    const uint32_t sb = s2u(smem);
    const int tid = threadIdx.x, lane = tid & 31;
    const int wn = (tid >> 5) & 3, wm = tid >> 7;
    const int g = blockIdx.z, n0 = blockIdx.x * 128, h0 = blockIdx.y * 128;

    const int cnt = g_cnt[g];
    if (n0 >= cnt) return;

    const __half* srcs[8];
    uint32_t dsts[8];
#pragma unroll
    for (int i = 0; i < 8; i++) {
        const int id = tid + i * 256;
        const int tile = id >> 10, rr = (id >> 3) & 127, cc = id & 7;
        const __half* p;
        if (tile == 0) {
            const int j = n0 + rr;
            const int jc = j < cnt ? j : cnt - 1;
            p = g_actf + ((size_t)g * N_TOK + jc) * IDIM;
        } else {
            p = g_wdf + ((size_t)g * HDIM + h0 + rr) * IDIM;
        }
        srcs[i] = p + cc * 8;
        dsts[i] = sb + tile * TILE_SZ + rr * ROWB + cc * 16;
    }

    float acc[4][4][4];
#pragma unroll
    for (int mt = 0; mt < 4; mt++)
#pragma unroll
        for (int j = 0; j < 4; j++)
#pragma unroll
            for (int e = 0; e < 4; e++) acc[mt][j][e] = 0.f;

#pragma unroll
    for (int i = 0; i < 8; i++) cpasync16(dsts[i], srcs[i]);
    CP_COMMIT();
#pragma unroll
    for (int i = 0; i < 8; i++) cpasync16(dsts[i] + STAGE_SZ, srcs[i] + KC);
    CP_COMMIT();

    for (int c = 0; c < NC2; c++) {
        CP_WAIT(1);
        __syncthreads();
        mma_stage(sb + (uint32_t)((c % NSTAGE) * STAGE_SZ), wm, wn, lane, acc);
        if (c + 2 < NC2) {
            const int k0 = (c + 2) * KC;
            const uint32_t so = (uint32_t)(((c + 2) % NSTAGE) * STAGE_SZ);
#pragma unroll
            for (int i = 0; i < 8; i++) cpasync16(dsts[i] + so, srcs[i] + k0);
        }
        CP_COMMIT();
    }

    // epilogue: scatter-add into y
    const int r = lane >> 2, cb = (lane & 3) * 2;
#pragma unroll
    for (int mt = 0; mt < 4; mt++) {
#pragma unroll
        for (int e2 = 0; e2 < 2; e2++) {
            const int row = wm * 64 + mt * 16 + r + e2 * 8;
            if (n0 + row >= cnt) continue;
            const int t = g_list[g][n0 + row];
            float* yrow = y + (size_t)t * HDIM + h0 + wn * 32;
#pragma unroll
            for (int nt = 0; nt < 4; nt++) {
                atomicAdd(yrow + nt * 8 + cb,     acc[mt][nt][e2 * 2]);
                atomicAdd(yrow + nt * 8 + cb + 1, acc[mt][nt][e2 * 2 + 1]);
            }
        }
    }
}

// ---------------------------------------------------------------------------
// Launch
// ---------------------------------------------------------------------------
extern "C" void kernel_launch(void* const* d_in, const int* in_sizes, int n_in,
                              void* d_out, int out_size)
{
    const float* x      = (const float*)d_in[0];
    const float* gate_w = (const float*)d_in[1];
    const float* mask_w = (const float*)d_in[2];
    const float* Wg     = (const float*)d_in[3];
    const float* Wu     = (const float*)d_in[4];
    const float* Wd     = (const float*)d_in[5];
    const void*  invmap = (const void*)d_in[6];
    float* y = (float*)d_out;
    (void)in_sizes; (void)n_in;

    cudaFuncSetAttribute(moe_g1_mma, cudaFuncAttributeMaxDynamicSharedMemorySize, SMEM_TOTAL);
    cudaFuncSetAttribute(moe_g2_mma, cudaFuncAttributeMaxDynamicSharedMemorySize, SMEM_TOTAL);

    __half* wdf;
    cudaGetSymbolAddress((void**)&wdf, g_wdf);

    // zero y (G2 scatter-adds); independent of everything else
    cudaMemsetAsync(y, 0, (size_t)out_size * sizeof(float));

    // Wd -> fp16 (only standalone conversion left)
    to_half<<<2048, 256>>>((const float4*)Wd, (uint2*)wdf,
                           (int)((size_t)NGRP * HDIM * IDIM / 4));

    // routing (+ x->fp16) -> compaction ; P projections (+ Wg/Wu->fp16)
    moe_route<<<N_TOK, 256>>>(x, gate_w, invmap);
    moe_compact<<<NGRP, 256>>>();
    moe_pproj<<<(NGRP * IDIM) / 8, 256>>>(Wg, Wu, mask_w);

    // G1: compacted gate/up GEMM + fused epilogue
    dim3 g1grid(N_TOK / 128, IDIM / 64, NGRP);
    moe_g1_mma<<<g1grid, 256, SMEM_TOTAL>>>();

    // G2: per-group down-proj, scatter-add into y
    dim3 g2grid(N_TOK / 128, HDIM / 128, NGRP);
    moe_g2_mma<<<g2grid, 256, SMEM_TOTAL>>>(y);
}